// round 3
// baseline (speedup 1.0000x reference)
#include <cuda_runtime.h>
#include <cstdint>
#include <cstddef>

// Problem constants
#define BSZ 64      // batch
#define TT  512     // timesteps
#define ISZ 512     // input size
#define HSZ 1024    // hidden size
#define G4  4096    // 4*HSZ
#define OSZ 128     // output size

// ---------------------------------------------------------------------------
// Scratch (static device allocations — no cudaMalloc allowed)
// g_gx layout: [t][n][b]  ->  ((t*G4 + n)*BSZ + b)   (b contiguous for the
// per-step epilogue's coalesced float4 reads)
// ---------------------------------------------------------------------------
__device__ float g_gx[(long long)TT * G4 * BSZ];   // 536 MB precomputed x-gates
__device__ float g_h[2][BSZ * HSZ];                // double-buffered hidden state
__device__ float g_c[BSZ * HSZ];                   // cell state

// ---------------------------------------------------------------------------
// Packed dual-fp32 helpers (FFMA2 path — sm_10x only via PTX f32x2)
// ---------------------------------------------------------------------------
__device__ __forceinline__ unsigned long long pk2(float lo, float hi) {
    unsigned long long r;
    asm("mov.b64 %0, {%1, %2};" : "=l"(r) : "f"(lo), "f"(hi));
    return r;
}
__device__ __forceinline__ void fma2(unsigned long long& d,
                                     unsigned long long a,
                                     unsigned long long b) {
    asm("fma.rn.f32x2 %0, %1, %2, %0;" : "+l"(d) : "l"(a), "l"(b));
}
__device__ __forceinline__ float2 upk2(unsigned long long v) {
    float2 r;
    asm("mov.b64 {%0, %1}, %2;" : "=f"(r.x), "=f"(r.y) : "l"(v));
    return r;
}

// ---------------------------------------------------------------------------
// Init: zero h (both buffers) and c
// ---------------------------------------------------------------------------
__global__ void k_init() {
    int i = blockIdx.x * blockDim.x + threadIdx.x;
    if (i < BSZ * HSZ) {
        g_h[0][i] = 0.f;
        g_h[1][i] = 0.f;
        g_c[i]    = 0.f;
    }
}

// ---------------------------------------------------------------------------
// Input GEMM:  g_gx[t][n][b] = bias[n] + sum_k x[b][t][k] * W_ih[n][k]
// M = T*B = 32768 (index m = t*64 + b), N = 4096, K = 512.
// CTA tile 128(n) x 128(m), 256 threads, 8x8 microtile in f32x2 pairs
// (pairs along m/batch, splat along n).
// ---------------------------------------------------------------------------
__global__ __launch_bounds__(256, 2)
void k_input_gemm(const float* __restrict__ x,
                  const float* __restrict__ Wih,
                  const float* __restrict__ bih,
                  const float* __restrict__ bhh) {
    const int mt = blockIdx.x;      // 0..255  (m tiles)
    const int nt = blockIdx.y;      // 0..31   (n tiles)
    __shared__ float As[16][132];   // W_ih tile, As[k][n_local]
    __shared__ float Bs[16][132];   // x tile,    Bs[k][m_local]

    const int tid = threadIdx.x;
    const int tx  = tid & 15;       // m groups of 8
    const int ty  = tid >> 4;       // n groups of 8
    const int n_base = nt * 128;
    const int m_base = mt * 128;

    unsigned long long acc[8][4];
#pragma unroll
    for (int i = 0; i < 8; ++i)
#pragma unroll
        for (int j = 0; j < 4; ++j) acc[i][j] = 0ULL;

    for (int k0 = 0; k0 < ISZ; k0 += 16) {
        // load W_ih tile: 128 rows x 16 k  (512 float4 / 256 thr = 2 each)
#pragma unroll
        for (int it = 0; it < 2; ++it) {
            int f  = it * 256 + tid;
            int r  = f >> 2;
            int kk = (f & 3) << 2;
            float4 v = *(const float4*)(Wih + (size_t)(n_base + r) * ISZ + k0 + kk);
            As[kk + 0][r] = v.x; As[kk + 1][r] = v.y;
            As[kk + 2][r] = v.z; As[kk + 3][r] = v.w;
        }
        // load x tile: 128 m x 16 k
#pragma unroll
        for (int it = 0; it < 2; ++it) {
            int f  = it * 256 + tid;
            int ml = f >> 2;
            int kk = (f & 3) << 2;
            int m  = m_base + ml;
            int b  = m & 63;
            int t  = m >> 6;
            float4 v = *(const float4*)(x + ((size_t)b * TT + t) * ISZ + k0 + kk);
            Bs[kk + 0][ml] = v.x; Bs[kk + 1][ml] = v.y;
            Bs[kk + 2][ml] = v.z; Bs[kk + 3][ml] = v.w;
        }
        __syncthreads();

#pragma unroll
        for (int k = 0; k < 16; ++k) {
            float a0[4], a1[4];
            *(float4*)a0 = *(const float4*)&As[k][ty * 8];
            *(float4*)a1 = *(const float4*)&As[k][ty * 8 + 4];
            ulonglong2 bp0 = *(const ulonglong2*)&Bs[k][tx * 8];
            ulonglong2 bp1 = *(const ulonglong2*)&Bs[k][tx * 8 + 4];
            unsigned long long bb[4] = {bp0.x, bp0.y, bp1.x, bp1.y};
#pragma unroll
            for (int i = 0; i < 4; ++i) {
                unsigned long long s0 = pk2(a0[i], a0[i]);
                unsigned long long s1 = pk2(a1[i], a1[i]);
#pragma unroll
                for (int j = 0; j < 4; ++j) {
                    fma2(acc[i][j],     s0, bb[j]);
                    fma2(acc[i + 4][j], s1, bb[j]);
                }
            }
        }
        __syncthreads();
    }

    // epilogue: add bias, write g_gx[t][n][b] (b-contiguous, float4 stores)
    const int m0 = m_base + tx * 8;      // 8 consecutive m -> same t, consecutive b
    const int b0 = m0 & 63;
    const int t  = m0 >> 6;
#pragma unroll
    for (int i = 0; i < 8; ++i) {
        int n = n_base + ty * 8 + i;
        float bias = bih[n] + bhh[n];
        float o[8];
#pragma unroll
        for (int j = 0; j < 4; ++j) {
            float2 v = upk2(acc[i][j]);
            o[2 * j]     = v.x + bias;
            o[2 * j + 1] = v.y + bias;
        }
        float* dst = g_gx + ((size_t)t * G4 + n) * BSZ + b0;
        *(float4*)(dst)     = make_float4(o[0], o[1], o[2], o[3]);
        *(float4*)(dst + 4) = make_float4(o[4], o[5], o[6], o[7]);
    }
}

// ---------------------------------------------------------------------------
// One LSTM step (fused recurrent GEMM + activations + c/h update).
// Grid 128 CTAs: CTA jt owns hidden units j in [jt*8, jt*8+8) for ALL 4 gates
// (32 W_hh rows, interleaved r = gate*8 + jj) x all 64 batches.
// 128 threads, microtile 4 rows x 4 batches as f32x2 pairs (pairs along batch).
// h double-buffered: reads g_h[t&1], writes g_h[(t+1)&1]  (no cross-CTA race).
// ---------------------------------------------------------------------------
__global__ __launch_bounds__(128, 1)
void k_step(const float* __restrict__ Whh, int t) {
    const int jt = blockIdx.x;      // 0..127
    const int j0 = jt * 8;
    __shared__ float ws[32][36];    // ws[k][r]  (r = gate*8 + jj)
    __shared__ float hs[32][68];    // hs[k][b]
    __shared__ float sg[32][68];    // staged gates sg[r][b]

    const float* __restrict__ hin = g_h[t & 1];
    float*       __restrict__ hout = g_h[(t + 1) & 1];

    const int tid = threadIdx.x;
    const int tx  = tid & 15;       // batch groups of 4  (16*4 = 64)
    const int ty  = tid >> 4;       // row groups of 4    (8*4  = 32)

    unsigned long long acc[4][2];
#pragma unroll
    for (int i = 0; i < 4; ++i) { acc[i][0] = 0ULL; acc[i][1] = 0ULL; }

    for (int k0 = 0; k0 < HSZ; k0 += 32) {
        // W_hh tile: 32 rows x 32 k = 256 float4 / 128 thr = 2 each
#pragma unroll
        for (int it = 0; it < 2; ++it) {
            int f    = it * 128 + tid;
            int r    = f >> 3;             // 8 float4 per row
            int kk   = (f & 7) << 2;
            int gate = r >> 3;
            int jj   = r & 7;
            int grow = gate * HSZ + j0 + jj;
            float4 v = *(const float4*)(Whh + (size_t)grow * HSZ + k0 + kk);
            ws[kk + 0][r] = v.x; ws[kk + 1][r] = v.y;
            ws[kk + 2][r] = v.z; ws[kk + 3][r] = v.w;
        }
        // h tile: 64 b x 32 k = 512 float4 / 128 thr = 4 each
#pragma unroll
        for (int it = 0; it < 4; ++it) {
            int f  = it * 128 + tid;
            int b  = f >> 3;
            int kk = (f & 7) << 2;
            float4 v = *(const float4*)(hin + (size_t)b * HSZ + k0 + kk);
            hs[kk + 0][b] = v.x; hs[kk + 1][b] = v.y;
            hs[kk + 2][b] = v.z; hs[kk + 3][b] = v.w;
        }
        __syncthreads();

#pragma unroll
        for (int k = 0; k < 32; ++k) {
            float4 wv = *(const float4*)&ws[k][ty * 4];
            ulonglong2 hv = *(const ulonglong2*)&hs[k][tx * 4];
            unsigned long long w0 = pk2(wv.x, wv.x);
            unsigned long long w1 = pk2(wv.y, wv.y);
            unsigned long long w2 = pk2(wv.z, wv.z);
            unsigned long long w3 = pk2(wv.w, wv.w);
            fma2(acc[0][0], w0, hv.x); fma2(acc[0][1], w0, hv.y);
            fma2(acc[1][0], w1, hv.x); fma2(acc[1][1], w1, hv.y);
            fma2(acc[2][0], w2, hv.x); fma2(acc[2][1], w2, hv.y);
            fma2(acc[3][0], w3, hv.x); fma2(acc[3][1], w3, hv.y);
        }
        __syncthreads();
    }

    // stage gates (+ precomputed x-part) into smem: sg[r][b]
    const size_t gxbase = (size_t)t * G4 * BSZ;
#pragma unroll
    for (int i = 0; i < 4; ++i) {
        int r    = ty * 4 + i;
        int gate = r >> 3;
        int jj   = r & 7;
        int n    = gate * HSZ + j0 + jj;
        float4 gxv = *(const float4*)(g_gx + gxbase + (size_t)n * BSZ + tx * 4);
        float2 v0 = upk2(acc[i][0]);
        float2 v1 = upk2(acc[i][1]);
        sg[r][tx * 4 + 0] = v0.x + gxv.x;
        sg[r][tx * 4 + 1] = v0.y + gxv.y;
        sg[r][tx * 4 + 2] = v1.x + gxv.z;
        sg[r][tx * 4 + 3] = v1.y + gxv.w;
    }
    __syncthreads();

    // activations + state update: 8 j x 64 b = 512 pairs, 4 per thread
#pragma unroll
    for (int p = tid; p < 512; p += 128) {
        int b  = p >> 3;
        int jj = p & 7;
        float ig = sg[jj][b];           // gate 0: i
        float fg = sg[8  + jj][b];      // gate 1: f
        float gg = sg[16 + jj][b];      // gate 2: g
        float og = sg[24 + jj][b];      // gate 3: o
        float si = 1.f / (1.f + expf(-ig));
        float sf = 1.f / (1.f + expf(-fg));
        float so = 1.f / (1.f + expf(-og));
        int idx = b * HSZ + j0 + jj;
        float c = sf * g_c[idx] + si * tanhf(gg);
        g_c[idx]  = c;
        hout[idx] = so * tanhf(c);
    }
}

// ---------------------------------------------------------------------------
// Classifier: out[b][o] = h_last[b] . W_clf[o] + b_clf[o]
// h_last lives in g_h[0] (T = 512 is even: step 511 wrote buffer (512&1)=0).
// ---------------------------------------------------------------------------
__global__ __launch_bounds__(128)
void k_classifier(const float* __restrict__ Wclf,
                  const float* __restrict__ bclf,
                  float* __restrict__ out) {
    int b = blockIdx.x;             // 64
    int o = threadIdx.x;            // 128
    __shared__ float hsh[HSZ];
    for (int k = threadIdx.x; k < HSZ; k += 128) hsh[k] = g_h[0][b * HSZ + k];
    __syncthreads();
    const float* w = Wclf + (size_t)o * HSZ;
    float acc = 0.f;
#pragma unroll 4
    for (int k = 0; k < HSZ; k += 4) {
        float4 wv = *(const float4*)(w + k);
        acc += wv.x * hsh[k] + wv.y * hsh[k + 1] + wv.z * hsh[k + 2] + wv.w * hsh[k + 3];
    }
    out[b * OSZ + o] = acc + bclf[o];
}

// ---------------------------------------------------------------------------
// Launch (graph-capturable: kernel launches only, default stream)
// Inputs: x, W_ih, W_hh, b_ih, b_hh, W_clf, b_clf
// ---------------------------------------------------------------------------
extern "C" void kernel_launch(void* const* d_in, const int* in_sizes, int n_in,
                              void* d_out, int out_size) {
    const float* x    = (const float*)d_in[0];
    const float* Wih  = (const float*)d_in[1];
    const float* Whh  = (const float*)d_in[2];
    const float* bih  = (const float*)d_in[3];
    const float* bhh  = (const float*)d_in[4];
    const float* Wclf = (const float*)d_in[5];
    const float* bclf = (const float*)d_in[6];
    float* out = (float*)d_out;

    k_init<<<256, 256>>>();
    k_input_gemm<<<dim3(256, 32), 256>>>(x, Wih, bih, bhh);
    for (int t = 0; t < TT; ++t)
        k_step<<<128, 128>>>(Whh, t);
    k_classifier<<<64, 128>>>(Wclf, bclf, out);
}

// round 4
// speedup vs baseline: 1.5616x; 1.5616x over previous
#include <cuda_runtime.h>
#include <cstdint>
#include <cstddef>

// Problem constants
#define BSZ 64      // batch
#define TT  512     // timesteps
#define ISZ 512     // input size
#define HSZ 1024    // hidden size
#define G4  4096    // 4*HSZ
#define OSZ 128     // output size
#define NCTA 128    // persistent CTAs (1 per SM, <=148 -> all co-resident)
#define NTHR 256

// ---------------------------------------------------------------------------
// Static device scratch (no cudaMalloc allowed)
// ---------------------------------------------------------------------------
__device__ float g_gx[(size_t)TT * G4 * BSZ];   // precomputed x-gates [t][n][b]
__device__ float g_hg[2][HSZ][BSZ];             // double-buffered h, TRANSPOSED [k][b]
__device__ unsigned g_bar_count;
__device__ unsigned g_bar_epoch;

// ---------------------------------------------------------------------------
// Packed dual-fp32 helpers (FFMA2 via PTX f32x2, sm_10x)
// ---------------------------------------------------------------------------
typedef unsigned long long u64;
__device__ __forceinline__ u64 pk2(float lo, float hi) {
    u64 r; asm("mov.b64 %0, {%1, %2};" : "=l"(r) : "f"(lo), "f"(hi)); return r;
}
__device__ __forceinline__ void fma2(u64& d, u64 a, u64 b) {
    asm("fma.rn.f32x2 %0, %1, %2, %0;" : "+l"(d) : "l"(a), "l"(b));
}
__device__ __forceinline__ float2 upk2(u64 v) {
    float2 r; asm("mov.b64 {%0, %1}, %2;" : "=f"(r.x), "=f"(r.y) : "l"(v)); return r;
}

// ---------------------------------------------------------------------------
// Reset barrier state (runs before the persistent kernel on every replay)
// ---------------------------------------------------------------------------
__global__ void k_zero_bar() { g_bar_count = 0; g_bar_epoch = 0; }

// ---------------------------------------------------------------------------
// Input GEMM (unchanged from R2):
// g_gx[t][n][b] = b_ih[n]+b_hh[n] + sum_k x[b][t][k] * W_ih[n][k]
// ---------------------------------------------------------------------------
__global__ __launch_bounds__(256, 2)
void k_input_gemm(const float* __restrict__ x,
                  const float* __restrict__ Wih,
                  const float* __restrict__ bih,
                  const float* __restrict__ bhh) {
    const int mt = blockIdx.x;
    const int nt = blockIdx.y;
    __shared__ float As[16][132];
    __shared__ float Bs[16][132];

    const int tid = threadIdx.x;
    const int tx  = tid & 15;
    const int ty  = tid >> 4;
    const int n_base = nt * 128;
    const int m_base = mt * 128;

    u64 acc[8][4];
#pragma unroll
    for (int i = 0; i < 8; ++i)
#pragma unroll
        for (int j = 0; j < 4; ++j) acc[i][j] = 0ULL;

    for (int k0 = 0; k0 < ISZ; k0 += 16) {
#pragma unroll
        for (int it = 0; it < 2; ++it) {
            int f  = it * 256 + tid;
            int r  = f >> 2;
            int kk = (f & 3) << 2;
            float4 v = *(const float4*)(Wih + (size_t)(n_base + r) * ISZ + k0 + kk);
            As[kk + 0][r] = v.x; As[kk + 1][r] = v.y;
            As[kk + 2][r] = v.z; As[kk + 3][r] = v.w;
        }
#pragma unroll
        for (int it = 0; it < 2; ++it) {
            int f  = it * 256 + tid;
            int ml = f >> 2;
            int kk = (f & 3) << 2;
            int m  = m_base + ml;
            int b  = m & 63;
            int t  = m >> 6;
            float4 v = *(const float4*)(x + ((size_t)b * TT + t) * ISZ + k0 + kk);
            Bs[kk + 0][ml] = v.x; Bs[kk + 1][ml] = v.y;
            Bs[kk + 2][ml] = v.z; Bs[kk + 3][ml] = v.w;
        }
        __syncthreads();

#pragma unroll
        for (int k = 0; k < 16; ++k) {
            float a0[4], a1[4];
            *(float4*)a0 = *(const float4*)&As[k][ty * 8];
            *(float4*)a1 = *(const float4*)&As[k][ty * 8 + 4];
            ulonglong2 bp0 = *(const ulonglong2*)&Bs[k][tx * 8];
            ulonglong2 bp1 = *(const ulonglong2*)&Bs[k][tx * 8 + 4];
            u64 bb[4] = {bp0.x, bp0.y, bp1.x, bp1.y};
#pragma unroll
            for (int i = 0; i < 4; ++i) {
                u64 s0 = pk2(a0[i], a0[i]);
                u64 s1 = pk2(a1[i], a1[i]);
#pragma unroll
                for (int j = 0; j < 4; ++j) {
                    fma2(acc[i][j],     s0, bb[j]);
                    fma2(acc[i + 4][j], s1, bb[j]);
                }
            }
        }
        __syncthreads();
    }

    const int m0 = m_base + tx * 8;
    const int b0 = m0 & 63;
    const int t  = m0 >> 6;
#pragma unroll
    for (int i = 0; i < 8; ++i) {
        int n = n_base + ty * 8 + i;
        float bias = bih[n] + bhh[n];
        float o[8];
#pragma unroll
        for (int j = 0; j < 4; ++j) {
            float2 v = upk2(acc[i][j]);
            o[2 * j]     = v.x + bias;
            o[2 * j + 1] = v.y + bias;
        }
        float* dst = g_gx + ((size_t)t * G4 + n) * BSZ + b0;
        *(float4*)(dst)     = make_float4(o[0], o[1], o[2], o[3]);
        *(float4*)(dst + 4) = make_float4(o[4], o[5], o[6], o[7]);
    }
}

// ---------------------------------------------------------------------------
// Grid barrier (all 128 CTAs co-resident by construction)
// ---------------------------------------------------------------------------
__device__ __forceinline__ void grid_barrier(unsigned& epoch) {
    __syncthreads();
    if (threadIdx.x == 0) {
        unsigned target = ++epoch;
        __threadfence();                       // release h writes
        if (atomicAdd(&g_bar_count, 1u) == NCTA - 1) {
            g_bar_count = 0;
            __threadfence();
            atomicExch(&g_bar_epoch, target);  // release
        } else {
            while (*(volatile unsigned*)&g_bar_epoch < target) __nanosleep(32);
            __threadfence();                   // acquire
        }
    } else {
        ++epoch;
    }
    __syncthreads();
}

// cp.async helpers
__device__ __forceinline__ void cpasync16(unsigned sdst, const void* src) {
    asm volatile("cp.async.cg.shared.global [%0], [%1], 16;" :: "r"(sdst), "l"(src) : "memory");
}
__device__ __forceinline__ void cp_commit() { asm volatile("cp.async.commit_group;" ::: "memory"); }
__device__ __forceinline__ void cp_wait1()  { asm volatile("cp.async.wait_group 1;"  ::: "memory"); }

// stage one 128-k chunk (32KB) of h into smem buffer
__device__ __forceinline__ void stage_chunk(const float* __restrict__ hin,
                                            float* __restrict__ hsbase,
                                            int c, int buf, int tid) {
    const float4* src = (const float4*)(hin + (size_t)c * 128 * BSZ);
    unsigned sd = (unsigned)__cvta_generic_to_shared(hsbase + (size_t)buf * 128 * BSZ);
#pragma unroll
    for (int i = 0; i < 8; ++i) {
        int idx = tid + i * NTHR;
        cpasync16(sd + idx * 16, src + idx);
    }
}

// ---------------------------------------------------------------------------
// Persistent LSTM kernel.
// 128 CTAs x 256 threads. CTA jt owns hidden units j in [jt*8, jt*8+8) for
// all 4 gates: 32 W_hh rows (r = gate*8+jj) x 64 batches.
// W_hh slice (128KB) resident in SMEM for all 512 steps; c in registers;
// h double-buffered in global [k][b], streamed per step via cp.async.
// Two k-parity teams of 128 threads each; thread microtile 4 rows x 4 batch,
// FFMA2 pairs along rows (W loads pre-paired, no W splats).
// ---------------------------------------------------------------------------
__global__ __launch_bounds__(NTHR, 1)
void k_lstm(const float* __restrict__ Whh) {
    extern __shared__ float smem[];
    float* ws = smem;                 // [1024][32]  W slice, k-major
    float* hs = ws + HSZ * 32;        // [2][128][64] h staging (and, post-loop, team-B partials)
    float* sg = hs + 2 * 128 * BSZ;   // [32][68] staged gates

    const int jt  = blockIdx.x;
    const int j0  = jt * 8;
    const int tid = threadIdx.x;
    const int team   = tid >> 7;      // 0 / 1 : k parity
    const int wg_tid = tid & 127;
    const int tx = wg_tid & 15;       // batch quad (16 x 4 = 64)
    const int ty = wg_tid >> 4;       // row quad   (8  x 4 = 32)

    // ---- load W slice into ws[k][r], r = gate*8 + jj (one-time) ----
    for (int r = 0; r < 32; ++r) {
        int gate = r >> 3, jj = r & 7;
        const float* wrow = Whh + (size_t)(gate * HSZ + j0 + jj) * HSZ;
        for (int k = tid * 4; k < HSZ; k += NTHR * 4) {
            float4 v = *(const float4*)(wrow + k);
            ws[(k + 0) * 32 + r] = v.x;
            ws[(k + 1) * 32 + r] = v.y;
            ws[(k + 2) * 32 + r] = v.z;
            ws[(k + 3) * 32 + r] = v.w;
        }
    }

    // ---- zero own h slice in buffer 0 (8 rows x 64 b = 128 float4) ----
    if (tid < 128)
        ((float4*)&g_hg[0][j0][0])[tid] = make_float4(0.f, 0.f, 0.f, 0.f);

    // ---- cell state in registers: thread owns cells (jj = tid>>5, b = (tid&31)*2 + e) ----
    float c0 = 0.f, c1 = 0.f;
    const int ajj = tid >> 5;             // 0..7
    const int ab0 = (tid & 31) * 2;       // 0..62

    unsigned epoch = 0;
    grid_barrier(epoch);                  // h buf0 zeroed everywhere

    for (int t = 0; t < TT; ++t) {
        const float* hin  = &g_hg[t & 1][0][0];
        float*       hout = &g_hg[(t + 1) & 1][0][0];

        // prefetch this step's gx slice rows (team A only; consumed in epilogue)
        float4 gxv[4];
        if (team == 0) {
            const size_t gxb = (size_t)t * G4 * BSZ;
#pragma unroll
            for (int i = 0; i < 4; ++i) {
                int r = ty * 4 + i;
                int n = (r >> 3) * HSZ + j0 + (r & 7);
                gxv[i] = *(const float4*)(g_gx + gxb + (size_t)n * BSZ + tx * 4);
            }
        }

        // pipeline prologue: chunks 0,1 in flight
        stage_chunk(hin, hs, 0, 0, tid); cp_commit();
        stage_chunk(hin, hs, 1, 1, tid); cp_commit();

        u64 a00 = 0, a01 = 0, a02 = 0, a03 = 0;   // rows (r0,r1) x b0..b3
        u64 a10 = 0, a11 = 0, a12 = 0, a13 = 0;   // rows (r2,r3) x b0..b3

        for (int c = 0; c < 8; ++c) {
            cp_wait1();
            __syncthreads();
            const float* hc = hs + (c & 1) * (128 * BSZ);
            const float* wp_base = ws + ((size_t)(c * 128 + team)) * 32 + ty * 4;
            const float* hp_base = hc + team * BSZ + tx * 4;
#pragma unroll 8
            for (int kk = 0; kk < 64; ++kk) {
                ulonglong2 wp = *(const ulonglong2*)(wp_base + (size_t)kk * 2 * 32);
                float4     hv = *(const float4*)(hp_base + (size_t)kk * 2 * BSZ);
                u64 h0 = pk2(hv.x, hv.x);
                u64 h1 = pk2(hv.y, hv.y);
                u64 h2 = pk2(hv.z, hv.z);
                u64 h3 = pk2(hv.w, hv.w);
                fma2(a00, wp.x, h0); fma2(a10, wp.y, h0);
                fma2(a01, wp.x, h1); fma2(a11, wp.y, h1);
                fma2(a02, wp.x, h2); fma2(a12, wp.y, h2);
                fma2(a03, wp.x, h3); fma2(a13, wp.y, h3);
            }
            __syncthreads();
            if (c + 2 < 8) stage_chunk(hin, hs, c + 2, c & 1, tid);
            cp_commit();
        }

        // unpack acc into per-row float4s (rows ty*4 .. ty*4+3, batches tx*4..+3)
        float2 l0 = upk2(a00), l1 = upk2(a01), l2 = upk2(a02), l3 = upk2(a03);
        float2 m0 = upk2(a10), m1 = upk2(a11), m2 = upk2(a12), m3 = upk2(a13);
        float4 row0 = make_float4(l0.x, l1.x, l2.x, l3.x);
        float4 row1 = make_float4(l0.y, l1.y, l2.y, l3.y);
        float4 row2 = make_float4(m0.x, m1.x, m2.x, m3.x);
        float4 row3 = make_float4(m0.y, m1.y, m2.y, m3.y);

        if (team == 1) {
            // team B: dump partials into ps (reuse hs region; mainloop is done)
            float* ps = hs;
            *(float4*)(ps + (ty * 4 + 0) * 68 + tx * 4) = row0;
            *(float4*)(ps + (ty * 4 + 1) * 68 + tx * 4) = row1;
            *(float4*)(ps + (ty * 4 + 2) * 68 + tx * 4) = row2;
            *(float4*)(ps + (ty * 4 + 3) * 68 + tx * 4) = row3;
        }
        __syncthreads();
        if (team == 0) {
            // team A: combine partials + gx into staged gates sg[r][b]
            const float* ps = hs;
#pragma unroll
            for (int i = 0; i < 4; ++i) {
                float4 mine = (i == 0) ? row0 : (i == 1) ? row1 : (i == 2) ? row2 : row3;
                float4 pv = *(const float4*)(ps + (ty * 4 + i) * 68 + tx * 4);
                float4 gv = gxv[i];
                float4 o = make_float4(mine.x + pv.x + gv.x,
                                       mine.y + pv.y + gv.y,
                                       mine.z + pv.z + gv.z,
                                       mine.w + pv.w + gv.w);
                *(float4*)(sg + (ty * 4 + i) * 68 + tx * 4) = o;
            }
        }
        __syncthreads();

        // activations + state update: 2 cells per thread (jj = ajj, b = ab0, ab0+1)
        {
            float2 iv = *(const float2*)(sg + ( 0 + ajj) * 68 + ab0);
            float2 fv = *(const float2*)(sg + ( 8 + ajj) * 68 + ab0);
            float2 gv = *(const float2*)(sg + (16 + ajj) * 68 + ab0);
            float2 ov = *(const float2*)(sg + (24 + ajj) * 68 + ab0);

            float si0 = 1.f / (1.f + __expf(-iv.x));
            float sf0 = 1.f / (1.f + __expf(-fv.x));
            float so0 = 1.f / (1.f + __expf(-ov.x));
            float si1 = 1.f / (1.f + __expf(-iv.y));
            float sf1 = 1.f / (1.f + __expf(-fv.y));
            float so1 = 1.f / (1.f + __expf(-ov.y));
            c0 = sf0 * c0 + si0 * tanhf(gv.x);
            c1 = sf1 * c1 + si1 * tanhf(gv.y);
            float2 hv2 = make_float2(so0 * tanhf(c0), so1 * tanhf(c1));
            *(float2*)(hout + (size_t)(j0 + ajj) * BSZ + ab0) = hv2;
        }

        grid_barrier(epoch);   // publishes h for step t+1; frees read buffer
    }
}

// ---------------------------------------------------------------------------
// Classifier: out[b][o] = h_last[b] . W_clf[o] + b_clf[o]
// h_last is g_hg[0] (step 511 wrote buffer (512)&1 = 0), layout [k][b].
// ---------------------------------------------------------------------------
__global__ __launch_bounds__(128)
void k_classifier(const float* __restrict__ Wclf,
                  const float* __restrict__ bclf,
                  float* __restrict__ out) {
    int b = blockIdx.x;
    int o = threadIdx.x;
    __shared__ float hsh[HSZ];
    for (int k = threadIdx.x; k < HSZ; k += 128) hsh[k] = g_hg[0][k][b];
    __syncthreads();
    const float* w = Wclf + (size_t)o * HSZ;
    float acc = 0.f;
#pragma unroll 4
    for (int k = 0; k < HSZ; k += 4) {
        float4 wv = *(const float4*)(w + k);
        acc += wv.x * hsh[k] + wv.y * hsh[k + 1] + wv.z * hsh[k + 2] + wv.w * hsh[k + 3];
    }
    out[b * OSZ + o] = acc + bclf[o];
}

// ---------------------------------------------------------------------------
// Launch (graph-capturable: kernel launches only)
// ---------------------------------------------------------------------------
extern "C" void kernel_launch(void* const* d_in, const int* in_sizes, int n_in,
                              void* d_out, int out_size) {
    const float* x    = (const float*)d_in[0];
    const float* Wih  = (const float*)d_in[1];
    const float* Whh  = (const float*)d_in[2];
    const float* bih  = (const float*)d_in[3];
    const float* bhh  = (const float*)d_in[4];
    const float* Wclf = (const float*)d_in[5];
    const float* bclf = (const float*)d_in[6];
    float* out = (float*)d_out;

    const int SMEM_BYTES = (HSZ * 32 + 2 * 128 * BSZ + 32 * 68) * (int)sizeof(float); // 205312
    cudaFuncSetAttribute(k_lstm, cudaFuncAttributeMaxDynamicSharedMemorySize, SMEM_BYTES);

    k_zero_bar<<<1, 1>>>();
    k_input_gemm<<<dim3(256, 32), 256>>>(x, Wih, bih, bhh);
    k_lstm<<<NCTA, NTHR, SMEM_BYTES>>>(Whh);
    k_classifier<<<64, 128>>>(Wclf, bclf, out);
}

// round 5
// speedup vs baseline: 1.7357x; 1.1115x over previous
#include <cuda_runtime.h>
#include <cstdint>
#include <cstddef>

// Problem constants
#define BSZ 64      // batch
#define TT  512     // timesteps
#define ISZ 512     // input size
#define HSZ 1024    // hidden size
#define G4  4096    // 4*HSZ
#define OSZ 128     // output size
#define NCTA 128    // persistent CTAs (1/SM, <=148 -> all co-resident)
#define NTHR 256

// ---------------------------------------------------------------------------
// Static device scratch (no cudaMalloc allowed)
// ---------------------------------------------------------------------------
__device__ float g_gx[(size_t)TT * G4 * BSZ];   // precomputed x-gates [t][n][b]
__device__ float g_hg[2][HSZ][BSZ];             // double-buffered h, [k][b]
__device__ unsigned g_flags[8];                 // per-k-chunk monotonic counters

// ---------------------------------------------------------------------------
// Packed dual-fp32 helpers (FFMA2 via PTX f32x2, sm_10x)
// ---------------------------------------------------------------------------
typedef unsigned long long u64;
__device__ __forceinline__ u64 pk2(float lo, float hi) {
    u64 r; asm("mov.b64 %0, {%1, %2};" : "=l"(r) : "f"(lo), "f"(hi)); return r;
}
__device__ __forceinline__ void fma2(u64& d, u64 a, u64 b) {
    asm("fma.rn.f32x2 %0, %1, %2, %0;" : "+l"(d) : "l"(a), "l"(b));
}
__device__ __forceinline__ float2 upk2(u64 v) {
    float2 r; asm("mov.b64 {%0, %1}, %2;" : "=f"(r.x), "=f"(r.y) : "l"(v)); return r;
}

// ---------------------------------------------------------------------------
// Zero h buffer 0 and the flags (runs before the persistent kernel)
// ---------------------------------------------------------------------------
__global__ void k_zero() {
    int i = blockIdx.x * blockDim.x + threadIdx.x;
    if (i < HSZ * BSZ) (&g_hg[0][0][0])[i] = 0.f;
    if (i < 8) g_flags[i] = 0u;
}

// ---------------------------------------------------------------------------
// Input GEMM:  g_gx[t][n][b] = b_ih[n]+b_hh[n] + sum_k x[b][t][k]*W_ih[n][k]
// ---------------------------------------------------------------------------
__global__ __launch_bounds__(256, 2)
void k_input_gemm(const float* __restrict__ x,
                  const float* __restrict__ Wih,
                  const float* __restrict__ bih,
                  const float* __restrict__ bhh) {
    const int mt = blockIdx.x;
    const int nt = blockIdx.y;
    __shared__ float As[16][132];
    __shared__ float Bs[16][132];

    const int tid = threadIdx.x;
    const int tx  = tid & 15;
    const int ty  = tid >> 4;
    const int n_base = nt * 128;
    const int m_base = mt * 128;

    u64 acc[8][4];
#pragma unroll
    for (int i = 0; i < 8; ++i)
#pragma unroll
        for (int j = 0; j < 4; ++j) acc[i][j] = 0ULL;

    for (int k0 = 0; k0 < ISZ; k0 += 16) {
#pragma unroll
        for (int it = 0; it < 2; ++it) {
            int f  = it * 256 + tid;
            int r  = f >> 2;
            int kk = (f & 3) << 2;
            float4 v = *(const float4*)(Wih + (size_t)(n_base + r) * ISZ + k0 + kk);
            As[kk + 0][r] = v.x; As[kk + 1][r] = v.y;
            As[kk + 2][r] = v.z; As[kk + 3][r] = v.w;
        }
#pragma unroll
        for (int it = 0; it < 2; ++it) {
            int f  = it * 256 + tid;
            int ml = f >> 2;
            int kk = (f & 3) << 2;
            int m  = m_base + ml;
            int b  = m & 63;
            int t  = m >> 6;
            float4 v = *(const float4*)(x + ((size_t)b * TT + t) * ISZ + k0 + kk);
            Bs[kk + 0][ml] = v.x; Bs[kk + 1][ml] = v.y;
            Bs[kk + 2][ml] = v.z; Bs[kk + 3][ml] = v.w;
        }
        __syncthreads();

#pragma unroll
        for (int k = 0; k < 16; ++k) {
            float a0[4], a1[4];
            *(float4*)a0 = *(const float4*)&As[k][ty * 8];
            *(float4*)a1 = *(const float4*)&As[k][ty * 8 + 4];
            ulonglong2 bp0 = *(const ulonglong2*)&Bs[k][tx * 8];
            ulonglong2 bp1 = *(const ulonglong2*)&Bs[k][tx * 8 + 4];
            u64 bb[4] = {bp0.x, bp0.y, bp1.x, bp1.y};
#pragma unroll
            for (int i = 0; i < 4; ++i) {
                u64 s0 = pk2(a0[i], a0[i]);
                u64 s1 = pk2(a1[i], a1[i]);
#pragma unroll
                for (int j = 0; j < 4; ++j) {
                    fma2(acc[i][j],     s0, bb[j]);
                    fma2(acc[i + 4][j], s1, bb[j]);
                }
            }
        }
        __syncthreads();
    }

    const int m0 = m_base + tx * 8;
    const int b0 = m0 & 63;
    const int t  = m0 >> 6;
#pragma unroll
    for (int i = 0; i < 8; ++i) {
        int n = n_base + ty * 8 + i;
        float bias = bih[n] + bhh[n];
        float o[8];
#pragma unroll
        for (int j = 0; j < 4; ++j) {
            float2 v = upk2(acc[i][j]);
            o[2 * j]     = v.x + bias;
            o[2 * j + 1] = v.y + bias;
        }
        float* dst = g_gx + ((size_t)t * G4 + n) * BSZ + b0;
        *(float4*)(dst)     = make_float4(o[0], o[1], o[2], o[3]);
        *(float4*)(dst + 4) = make_float4(o[4], o[5], o[6], o[7]);
    }
}

// cp.async helpers
__device__ __forceinline__ void cpasync16(unsigned sdst, const void* src) {
    asm volatile("cp.async.cg.shared.global [%0], [%1], 16;" :: "r"(sdst), "l"(src) : "memory");
}
__device__ __forceinline__ void cp_commit() { asm volatile("cp.async.commit_group;" ::: "memory"); }
__device__ __forceinline__ void cp_wait1()  { asm volatile("cp.async.wait_group 1;"  ::: "memory"); }

// stage one 128-k chunk (32KB) of h into smem buffer
__device__ __forceinline__ void stage_chunk(const float* __restrict__ hin,
                                            float* __restrict__ hsbase,
                                            int c, int buf, int tid) {
    const float4* src = (const float4*)(hin + (size_t)c * 128 * BSZ);
    unsigned sd = (unsigned)__cvta_generic_to_shared(hsbase + (size_t)buf * 128 * BSZ);
#pragma unroll
    for (int i = 0; i < 8; ++i) {
        int idx = tid + i * NTHR;
        cpasync16(sd + idx * 16, src + idx);
    }
}

// flag ops (release/acquire, GPU scope)
__device__ __forceinline__ void flag_release_inc(unsigned* f) {
    asm volatile("red.release.gpu.global.add.u32 [%0], %1;" :: "l"(f), "r"(1u) : "memory");
}
__device__ __forceinline__ unsigned flag_acquire_ld(const unsigned* f) {
    unsigned v;
    asm volatile("ld.acquire.gpu.global.u32 %0, [%1];" : "=r"(v) : "l"(f) : "memory");
    return v;
}

// ---------------------------------------------------------------------------
// Persistent LSTM kernel.
// 128 CTAs x 256 threads. CTA jt owns hidden units [jt*8, jt*8+8) for all 4
// gates: 32 W_hh rows (r = gate*8+jj) x 64 batches.
// W_hh slice (128KB) SMEM-resident for all steps. h double-buffered in global
// [k][b], streamed per step via cp.async (stays L2-resident).
// Thread microtile 8 rows x 4 batches (FFMA2 pairs along rows); 4 k-teams of
// 64 threads each. Per-step sync via monotonic per-chunk flags
// (release/acquire), no full grid barrier.
// ---------------------------------------------------------------------------
__global__ __launch_bounds__(NTHR, 1)
void k_lstm(const float* __restrict__ Whh) {
    extern __shared__ float smem[];
    float* ws = smem;                 // [1024][32]  W slice, k-major
    float* hs = ws + HSZ * 32;        // [2][128][64] h staging; post-loop: ps[4][32][68]
    float* sg = hs + 2 * 128 * BSZ;   // [32][68] staged gates

    const int jt  = blockIdx.x;
    const int j0  = jt * 8;
    const int tid = threadIdx.x;
    const int g   = tid >> 6;         // k-team 0..3
    const int tt  = tid & 63;
    const int tx  = tt & 15;          // batch quad (16 x 4 = 64)
    const int ty  = tt >> 4;          // row octet  (4  x 8 = 32)

    // ---- load W slice into ws[k][r], r = gate*8 + jj (one-time) ----
    for (int r = 0; r < 32; ++r) {
        int gate = r >> 3, jj = r & 7;
        const float* wrow = Whh + (size_t)(gate * HSZ + j0 + jj) * HSZ;
        for (int k = tid * 4; k < HSZ; k += NTHR * 4) {
            float4 v = *(const float4*)(wrow + k);
            ws[(k + 0) * 32 + r] = v.x;
            ws[(k + 1) * 32 + r] = v.y;
            ws[(k + 2) * 32 + r] = v.z;
            ws[(k + 3) * 32 + r] = v.w;
        }
    }

    // cell state in registers: thread owns cells (jj = tid>>5, b = (tid&31)*2 + e)
    float c0 = 0.f, c1 = 0.f;
    const int ajj = tid >> 5;             // 0..7
    const int ab0 = (tid & 31) * 2;       // 0..62

    // epilogue phase-1 mapping: thread -> (row er, 8 batches from eb)
    const int er = tid >> 3;              // 0..31
    const int eb = (tid & 7) * 8;         // 0..56
    const int en = (er >> 3) * HSZ + j0 + (er & 7);
    const float* gx_thread = g_gx + (size_t)en * BSZ + eb;

    const int my_chunk = jt >> 4;         // this CTA's producer chunk

    for (int t = 0; t < TT; ++t) {
        const float* hin  = &g_hg[t & 1][0][0];
        float*       hout = &g_hg[(t + 1) & 1][0][0];

        // ---- wait for h^t fully published (flags are monotonic counters) ----
        if (t && tid == 0) {
            unsigned tgt = 16u * (unsigned)t;
            for (int c = 0; c < 8; ++c)
                while (flag_acquire_ld(&g_flags[c]) < tgt) { }
        }
        __syncthreads();

        // prefetch this step's gx for the epilogue (DRAM latency hidden by mainloop)
        const float* gxp = gx_thread + (size_t)t * G4 * BSZ;
        float4 gxa = *(const float4*)(gxp);
        float4 gxb = *(const float4*)(gxp + 4);

        // pipeline prologue: chunks 0,1 in flight
        stage_chunk(hin, hs, 0, 0, tid); cp_commit();
        stage_chunk(hin, hs, 1, 1, tid); cp_commit();

        u64 acc[4][4];   // [row-pair p][batch j]; pair = rows (ty*8+2p, ty*8+2p+1)
#pragma unroll
        for (int p = 0; p < 4; ++p)
#pragma unroll
            for (int j = 0; j < 4; ++j) acc[p][j] = 0ULL;

        for (int c = 0; c < 8; ++c) {
            cp_wait1();
            __syncthreads();
            const float* wp = ws + (size_t)(c * 128 + g) * 32 + ty * 8;
            const float* hp = hs + (size_t)(c & 1) * (128 * BSZ) + g * BSZ + tx * 4;
#pragma unroll 8
            for (int kk = 0; kk < 32; ++kk) {
                ulonglong2 w01 = *(const ulonglong2*)(wp + (size_t)kk * 128);
                ulonglong2 w23 = *(const ulonglong2*)(wp + (size_t)kk * 128 + 4);
                float4     hv  = *(const float4*)(hp + (size_t)kk * 256);
                u64 h0 = pk2(hv.x, hv.x);
                u64 h1 = pk2(hv.y, hv.y);
                u64 h2 = pk2(hv.z, hv.z);
                u64 h3 = pk2(hv.w, hv.w);
                fma2(acc[0][0], w01.x, h0); fma2(acc[1][0], w01.y, h0);
                fma2(acc[2][0], w23.x, h0); fma2(acc[3][0], w23.y, h0);
                fma2(acc[0][1], w01.x, h1); fma2(acc[1][1], w01.y, h1);
                fma2(acc[2][1], w23.x, h1); fma2(acc[3][1], w23.y, h1);
                fma2(acc[0][2], w01.x, h2); fma2(acc[1][2], w01.y, h2);
                fma2(acc[2][2], w23.x, h2); fma2(acc[3][2], w23.y, h2);
                fma2(acc[0][3], w01.x, h3); fma2(acc[1][3], w01.y, h3);
                fma2(acc[2][3], w23.x, h3); fma2(acc[3][3], w23.y, h3);
            }
            __syncthreads();
            if (c + 2 < 8) stage_chunk(hin, hs, c + 2, c & 1, tid);
            cp_commit();
        }

        // ---- dump per-team partials into ps (reuse hs; mainloop done) ----
        float* ps = hs;   // [4][32][68]
#pragma unroll
        for (int p = 0; p < 4; ++p)
#pragma unroll
            for (int j = 0; j < 4; ++j) {
                float2 v = upk2(acc[p][j]);
                ps[((size_t)g * 32 + ty * 8 + 2 * p    ) * 68 + tx * 4 + j] = v.x;
                ps[((size_t)g * 32 + ty * 8 + 2 * p + 1) * 68 + tx * 4 + j] = v.y;
            }
        __syncthreads();

        // ---- phase 1: cross-team reduce + gx -> sg[r][b] ----
        {
            const float* p0 = ps + (size_t)(0 * 32 + er) * 68 + eb;
            const float* p1 = ps + (size_t)(1 * 32 + er) * 68 + eb;
            const float* p2 = ps + (size_t)(2 * 32 + er) * 68 + eb;
            const float* p3 = ps + (size_t)(3 * 32 + er) * 68 + eb;
            float4 a0 = *(const float4*)(p0), a1 = *(const float4*)(p1);
            float4 a2 = *(const float4*)(p2), a3 = *(const float4*)(p3);
            float4 s0 = make_float4(a0.x + a1.x + a2.x + a3.x + gxa.x,
                                    a0.y + a1.y + a2.y + a3.y + gxa.y,
                                    a0.z + a1.z + a2.z + a3.z + gxa.z,
                                    a0.w + a1.w + a2.w + a3.w + gxa.w);
            float4 b0 = *(const float4*)(p0 + 4), b1 = *(const float4*)(p1 + 4);
            float4 b2 = *(const float4*)(p2 + 4), b3 = *(const float4*)(p3 + 4);
            float4 s1 = make_float4(b0.x + b1.x + b2.x + b3.x + gxb.x,
                                    b0.y + b1.y + b2.y + b3.y + gxb.y,
                                    b0.z + b1.z + b2.z + b3.z + gxb.z,
                                    b0.w + b1.w + b2.w + b3.w + gxb.w);
            *(float4*)(sg + (size_t)er * 68 + eb)     = s0;
            *(float4*)(sg + (size_t)er * 68 + eb + 4) = s1;
        }
        __syncthreads();

        // ---- phase 2: activations + state update (2 cells/thread) ----
        {
            float2 iv = *(const float2*)(sg + ( 0 + ajj) * 68 + ab0);
            float2 fv = *(const float2*)(sg + ( 8 + ajj) * 68 + ab0);
            float2 gv = *(const float2*)(sg + (16 + ajj) * 68 + ab0);
            float2 ov = *(const float2*)(sg + (24 + ajj) * 68 + ab0);

            float si0 = 1.f / (1.f + __expf(-iv.x));
            float sf0 = 1.f / (1.f + __expf(-fv.x));
            float so0 = 1.f / (1.f + __expf(-ov.x));
            float si1 = 1.f / (1.f + __expf(-iv.y));
            float sf1 = 1.f / (1.f + __expf(-fv.y));
            float so1 = 1.f / (1.f + __expf(-ov.y));
            c0 = sf0 * c0 + si0 * tanhf(gv.x);
            c1 = sf1 * c1 + si1 * tanhf(gv.y);
            float2 hv2 = make_float2(so0 * tanhf(c0), so1 * tanhf(c1));
            *(float2*)(hout + (size_t)(j0 + ajj) * BSZ + ab0) = hv2;
        }

        // ---- publish h^{t+1} ----
        __syncthreads();                       // all hout stores done (CTA scope)
        if (tid == 0) flag_release_inc(&g_flags[my_chunk]);
    }
}

// ---------------------------------------------------------------------------
// Classifier: out[b][o] = h_last[b] . W_clf[o] + b_clf[o]
// h_last is g_hg[0] (step 511 wrote buffer (512)&1 = 0), layout [k][b].
// ---------------------------------------------------------------------------
__global__ __launch_bounds__(128)
void k_classifier(const float* __restrict__ Wclf,
                  const float* __restrict__ bclf,
                  float* __restrict__ out) {
    int b = blockIdx.x;
    int o = threadIdx.x;
    __shared__ float hsh[HSZ];
    for (int k = threadIdx.x; k < HSZ; k += 128) hsh[k] = g_hg[0][k][b];
    __syncthreads();
    const float* w = Wclf + (size_t)o * HSZ;
    float acc = 0.f;
#pragma unroll 4
    for (int k = 0; k < HSZ; k += 4) {
        float4 wv = *(const float4*)(w + k);
        acc += wv.x * hsh[k] + wv.y * hsh[k + 1] + wv.z * hsh[k + 2] + wv.w * hsh[k + 3];
    }
    out[b * OSZ + o] = acc + bclf[o];
}

// ---------------------------------------------------------------------------
// Launch (graph-capturable: kernel launches only)
// ---------------------------------------------------------------------------
extern "C" void kernel_launch(void* const* d_in, const int* in_sizes, int n_in,
                              void* d_out, int out_size) {
    const float* x    = (const float*)d_in[0];
    const float* Wih  = (const float*)d_in[1];
    const float* Whh  = (const float*)d_in[2];
    const float* bih  = (const float*)d_in[3];
    const float* bhh  = (const float*)d_in[4];
    const float* Wclf = (const float*)d_in[5];
    const float* bclf = (const float*)d_in[6];
    float* out = (float*)d_out;

    const int SMEM_BYTES = (HSZ * 32 + 2 * 128 * BSZ + 32 * 68) * (int)sizeof(float); // 205312
    cudaFuncSetAttribute(k_lstm, cudaFuncAttributeMaxDynamicSharedMemorySize, SMEM_BYTES);

    k_zero<<<256, 256>>>();
    k_input_gemm<<<dim3(256, 32), 256>>>(x, Wih, bih, bhh);
    k_lstm<<<NCTA, NTHR, SMEM_BYTES>>>(Whh);
    k_classifier<<<64, 128>>>(Wclf, bclf, out);
}

// round 7
// speedup vs baseline: 2.3720x; 1.3666x over previous
#include <cuda_runtime.h>
#include <cuda_bf16.h>
#include <cstdint>
#include <cstddef>

// Problem constants
#define BSZ 64      // batch
#define TT  512     // timesteps
#define ISZ 512     // input size
#define HSZ 1024    // hidden size
#define G4  4096    // 4*HSZ
#define OSZ 128     // output size
#define NCTA 128    // persistent CTAs (1/SM, <=148 -> all co-resident)
#define NTHR 128

// ---------------------------------------------------------------------------
// Static device scratch
// ---------------------------------------------------------------------------
__device__ __align__(16) float g_gx[(size_t)TT * G4 * BSZ];     // x-gates [t][n][b]
__device__ __align__(16) __nv_bfloat16 g_hbhi[2][BSZ][HSZ];     // h bf16 hi, [buf][b][k]
__device__ __align__(16) __nv_bfloat16 g_hblo[2][BSZ][HSZ];     // h bf16 lo
__device__ __align__(16) float g_hfin[BSZ * HSZ];               // final h [b][k]
__device__ unsigned g_done;    // monotonic: 128*(t+1) when all CTAs published h^{t+1}
__device__ unsigned g_rdone;   // monotonic: 128*(t+1) when all CTAs finished reading h^t

typedef unsigned long long u64;

// ---------------------------------------------------------------------------
// Helpers
// ---------------------------------------------------------------------------
__device__ __forceinline__ u64 pk2(float lo, float hi) {
    u64 r; asm("mov.b64 %0, {%1, %2};" : "=l"(r) : "f"(lo), "f"(hi)); return r;
}
__device__ __forceinline__ void fma2(u64& d, u64 a, u64 b) {
    asm("fma.rn.f32x2 %0, %1, %2, %0;" : "+l"(d) : "l"(a), "l"(b));
}
__device__ __forceinline__ float2 upk2(u64 v) {
    float2 r; asm("mov.b64 {%0, %1}, %2;" : "=f"(r.x), "=f"(r.y) : "l"(v)); return r;
}
__device__ __forceinline__ unsigned pkbf(float a, float b) {   // low half=bf16(a), high=bf16(b)
    unsigned r; asm("cvt.rn.bf16x2.f32 %0, %1, %2;" : "=r"(r) : "f"(b), "f"(a)); return r;
}
__device__ __forceinline__ unsigned smem_u32(const void* p) {
    unsigned a;
    asm("{ .reg .u64 t; cvta.to.shared.u64 t, %1; cvt.u32.u64 %0, t; }" : "=r"(a) : "l"(p));
    return a;
}
__device__ __forceinline__ void cpasync16(unsigned sdst, const void* src) {
    asm volatile("cp.async.cg.shared.global [%0], [%1], 16;" :: "r"(sdst), "l"(src) : "memory");
}
__device__ __forceinline__ void cp_commit() { asm volatile("cp.async.commit_group;" ::: "memory"); }
__device__ __forceinline__ void cp_wait1()  { asm volatile("cp.async.wait_group 1;" ::: "memory"); }
__device__ __forceinline__ void flag_rel(unsigned* f) {
    asm volatile("red.release.gpu.global.add.u32 [%0], %1;" :: "l"(f), "r"(1u) : "memory");
}
__device__ __forceinline__ unsigned flag_acq(const unsigned* f) {
    unsigned v;
    asm volatile("ld.acquire.gpu.global.u32 %0, [%1];" : "=r"(v) : "l"(f) : "memory");
    return v;
}
// ldmatrix x4 (non-transposed, b16)
__device__ __forceinline__ void ldsm4(unsigned* r, unsigned addr) {
    asm volatile("ldmatrix.sync.aligned.m8n8.x4.shared.b16 {%0,%1,%2,%3}, [%4];"
                 : "=r"(r[0]), "=r"(r[1]), "=r"(r[2]), "=r"(r[3]) : "r"(addr));
}
// mma m16n8k16 row.col f32 += bf16*bf16
__device__ __forceinline__ void mma16816(float* d, const unsigned* a, unsigned b0, unsigned b1) {
    asm volatile(
        "mma.sync.aligned.m16n8k16.row.col.f32.bf16.bf16.f32 "
        "{%0,%1,%2,%3}, {%4,%5,%6,%7}, {%8,%9}, {%0,%1,%2,%3};"
        : "+f"(d[0]), "+f"(d[1]), "+f"(d[2]), "+f"(d[3])
        : "r"(a[0]), "r"(a[1]), "r"(a[2]), "r"(a[3]), "r"(b0), "r"(b1));
}

// ---------------------------------------------------------------------------
// Zero h buffer 0 and flags
// ---------------------------------------------------------------------------
__global__ void k_zero() {
    int i = blockIdx.x * blockDim.x + threadIdx.x;
    if (i < 32768) {                       // 65536 bf16 per array = 32768 uints
        ((unsigned*)&g_hbhi[0][0][0])[i] = 0u;
        ((unsigned*)&g_hblo[0][0][0])[i] = 0u;
    }
    if (i == 0) { g_done = 0u; g_rdone = 0u; }
}

// ---------------------------------------------------------------------------
// Input GEMM (FFMA2, proven): g_gx[t][n][b] = b_ih[n]+b_hh[n] + x@W_ih^T
// ---------------------------------------------------------------------------
__global__ __launch_bounds__(256, 2)
void k_input_gemm(const float* __restrict__ x,
                  const float* __restrict__ Wih,
                  const float* __restrict__ bih,
                  const float* __restrict__ bhh) {
    const int mt = blockIdx.x;
    const int nt = blockIdx.y;
    __shared__ float As[16][132];
    __shared__ float Bs[16][132];

    const int tid = threadIdx.x;
    const int tx  = tid & 15;
    const int ty  = tid >> 4;
    const int n_base = nt * 128;
    const int m_base = mt * 128;

    u64 acc[8][4];
#pragma unroll
    for (int i = 0; i < 8; ++i)
#pragma unroll
        for (int j = 0; j < 4; ++j) acc[i][j] = 0ULL;

    for (int k0 = 0; k0 < ISZ; k0 += 16) {
#pragma unroll
        for (int it = 0; it < 2; ++it) {
            int f  = it * 256 + tid;
            int r  = f >> 2;
            int kk = (f & 3) << 2;
            float4 v = *(const float4*)(Wih + (size_t)(n_base + r) * ISZ + k0 + kk);
            As[kk + 0][r] = v.x; As[kk + 1][r] = v.y;
            As[kk + 2][r] = v.z; As[kk + 3][r] = v.w;
        }
#pragma unroll
        for (int it = 0; it < 2; ++it) {
            int f  = it * 256 + tid;
            int ml = f >> 2;
            int kk = (f & 3) << 2;
            int m  = m_base + ml;
            int b  = m & 63;
            int t  = m >> 6;
            float4 v = *(const float4*)(x + ((size_t)b * TT + t) * ISZ + k0 + kk);
            Bs[kk + 0][ml] = v.x; Bs[kk + 1][ml] = v.y;
            Bs[kk + 2][ml] = v.z; Bs[kk + 3][ml] = v.w;
        }
        __syncthreads();

#pragma unroll
        for (int k = 0; k < 16; ++k) {
            float a0[4], a1[4];
            *(float4*)a0 = *(const float4*)&As[k][ty * 8];
            *(float4*)a1 = *(const float4*)&As[k][ty * 8 + 4];
            ulonglong2 bp0 = *(const ulonglong2*)&Bs[k][tx * 8];
            ulonglong2 bp1 = *(const ulonglong2*)&Bs[k][tx * 8 + 4];
            u64 bb[4] = {bp0.x, bp0.y, bp1.x, bp1.y};
#pragma unroll
            for (int i = 0; i < 4; ++i) {
                u64 s0 = pk2(a0[i], a0[i]);
                u64 s1 = pk2(a1[i], a1[i]);
#pragma unroll
                for (int j = 0; j < 4; ++j) {
                    fma2(acc[i][j],     s0, bb[j]);
                    fma2(acc[i + 4][j], s1, bb[j]);
                }
            }
        }
        __syncthreads();
    }

    const int m0 = m_base + tx * 8;
    const int b0 = m0 & 63;
    const int t  = m0 >> 6;
#pragma unroll
    for (int i = 0; i < 8; ++i) {
        int n = n_base + ty * 8 + i;
        float bias = bih[n] + bhh[n];
        float o[8];
#pragma unroll
        for (int j = 0; j < 4; ++j) {
            float2 v = upk2(acc[i][j]);
            o[2 * j]     = v.x + bias;
            o[2 * j + 1] = v.y + bias;
        }
        float* dst = g_gx + ((size_t)t * G4 + n) * BSZ + b0;
        *(float4*)(dst)     = make_float4(o[0], o[1], o[2], o[3]);
        *(float4*)(dst + 4) = make_float4(o[4], o[5], o[6], o[7]);
    }
}

// ---------------------------------------------------------------------------
// SMEM layout for k_lstm (dynamic):
//   Whi : 32 rows x 1032 bf16 (stride 2064B)            [0      , 66048)
//   Wlo : same                                           [66048  , 132096)
//   B   : 2 bufs x { hi 64x136 bf16 | lo 64x136 bf16 }   [132096 , 201728)
//         buf stride 34816B; lo at +17408 within buf; row stride 272B
//   sg  : 32 x 66 f32                                    [201728 , 210176)
// ---------------------------------------------------------------------------
#define W_STRIDE   2064
#define WLO_OFF    66048
#define B_OFF      132096
#define B_BUFSZ    34816
#define B_LO_OFF   17408
#define B_STRIDE   272
#define SG_OFF     201728
#define SMEM_TOTAL 210176

// stage one 128-k chunk of h (hi+lo) into smem buffer (c&1)
__device__ __forceinline__ void stage_chunk(int p, int c, unsigned smem_base, int tid) {
    const char* shi = (const char*)&g_hbhi[p][0][0];
    const char* slo = (const char*)&g_hblo[p][0][0];
    unsigned dhi = smem_base + B_OFF + (unsigned)(c & 1) * B_BUFSZ;
    unsigned dlo = dhi + B_LO_OFF;
    int koff = c * 256;                    // byte offset of chunk within a row
#pragma unroll
    for (int i = 0; i < 8; ++i) {
        int f   = tid + i * NTHR;          // 0..1023
        int row = f >> 4;
        int seg = (f & 15) << 4;
        cpasync16(dhi + (unsigned)row * B_STRIDE + seg, shi + (size_t)row * 2048 + koff + seg);
        cpasync16(dlo + (unsigned)row * B_STRIDE + seg, slo + (size_t)row * 2048 + koff + seg);
    }
}

// ---------------------------------------------------------------------------
// Persistent tensor-core LSTM (mma.sync bf16, 3-way split for fp32 accuracy).
// CTA jt owns hidden units [8jt, 8jt+8) x 4 gates = 32 gate-rows x 64 batch,
// full K=1024. W resident in SMEM; h streamed in 8 double-buffered chunks.
// Warp w computes all 32 rows x batches [16w,16w+16).
// ---------------------------------------------------------------------------
__global__ __launch_bounds__(NTHR, 1)
void k_lstm(const float* __restrict__ Whh) {
    extern __shared__ __align__(16) char smem[];
    const unsigned sb = smem_u32(smem);
    float* sg = (float*)(smem + SG_OFF);

    const int jt   = blockIdx.x;
    const int tid  = threadIdx.x;
    const int w    = tid >> 5;
    const int lane = tid & 31;

    // ---- one-time: W rows -> SMEM bf16 hi/lo (row lr = gate*8+jj) ----
#pragma unroll
    for (int it = 0; it < 64; ++it) {
        int f   = tid + it * NTHR;         // 8192 float4 total
        int row = f >> 8;                  // 0..31
        int k4  = (f & 255) << 2;          // 0..1020
        int gate = row >> 3, jj = row & 7;
        const float* src = Whh + (size_t)(gate * HSZ + jt * 8 + jj) * HSZ + k4;
        float4 v = *(const float4*)src;
        float xh = __bfloat162float(__float2bfloat16(v.x));
        float yh = __bfloat162float(__float2bfloat16(v.y));
        float zh = __bfloat162float(__float2bfloat16(v.z));
        float wh = __bfloat162float(__float2bfloat16(v.w));
        uint2 hi = make_uint2(pkbf(v.x, v.y), pkbf(v.z, v.w));
        uint2 lo = make_uint2(pkbf(v.x - xh, v.y - yh), pkbf(v.z - zh, v.w - wh));
        *(uint2*)(smem + (size_t)row * W_STRIDE + k4 * 2)           = hi;
        *(uint2*)(smem + WLO_OFF + (size_t)row * W_STRIDE + k4 * 2) = lo;
    }
    __syncthreads();

    // ldmatrix base addresses (fixed per thread)
    const unsigned aBase = sb + (unsigned)(lane & 15) * W_STRIDE + ((lane >> 4) & 1) * 16u;
    const unsigned bRow  = (unsigned)(w * 16 + (lane & 7) + ((lane >> 4) & 1) * 8);
    const unsigned bBase = sb + B_OFF + bRow * B_STRIDE + ((lane >> 3) & 1) * 16u;

    // activation mapping: thread -> (jj0 = (tid>>6)*4, b = tid&63), 4 cells
    const int ab  = tid & 63;
    const int jj0 = (tid >> 6) * 4;
    float cc[4] = {0.f, 0.f, 0.f, 0.f};

    // fragment epilogue positions
    const int g   = lane >> 2;
    const int tig = lane & 3;

    for (int t = 0; t < TT; ++t) {
        const int p = t & 1;

        // ---- wait: all CTAs published h^t ----
        if (t && tid == 0)
            while (flag_acq(&g_done) < 128u * (unsigned)t) { }
        __syncthreads();

        // ---- prefetch this step's gx (consumed in activation) ----
        float gxr[16];
#pragma unroll
        for (int gi = 0; gi < 4; ++gi)
#pragma unroll
            for (int i = 0; i < 4; ++i)
                gxr[gi * 4 + i] = __ldg(g_gx + ((size_t)t * G4 + gi * HSZ + jt * 8 + jj0 + i) * BSZ + ab);

        // ---- pipeline prologue ----
        stage_chunk(p, 0, sb, tid); cp_commit();
        stage_chunk(p, 1, sb, tid); cp_commit();

        float d[2][2][4];
#pragma unroll
        for (int mt = 0; mt < 2; ++mt)
#pragma unroll
            for (int nt = 0; nt < 2; ++nt)
#pragma unroll
                for (int r = 0; r < 4; ++r) d[mt][nt][r] = 0.f;

        for (int c = 0; c < 8; ++c) {
            cp_wait1();
            __syncthreads();
            if (c == 7 && tid == 0) flag_rel(&g_rdone);   // all h^t reads landed

            const unsigned ahi = aBase + (unsigned)c * 256u;
            const unsigned alo = ahi + WLO_OFF;
            const unsigned bhi = bBase + (unsigned)(c & 1) * B_BUFSZ;
            const unsigned blo = bhi + B_LO_OFF;
#pragma unroll
            for (int ks = 0; ks < 8; ++ks) {
                unsigned Ah0[4], Ah1[4], Al0[4], Al1[4], Bh[4], Bl[4];
                ldsm4(Ah0, ahi + ks * 32u);
                ldsm4(Ah1, ahi + ks * 32u + 16u * W_STRIDE);
                ldsm4(Al0, alo + ks * 32u);
                ldsm4(Al1, alo + ks * 32u + 16u * W_STRIDE);
                ldsm4(Bh,  bhi + ks * 32u);
                ldsm4(Bl,  blo + ks * 32u);
                // Wh * h_hi
                mma16816(d[0][0], Ah0, Bh[0], Bh[1]);
                mma16816(d[0][1], Ah0, Bh[2], Bh[3]);
                mma16816(d[1][0], Ah1, Bh[0], Bh[1]);
                mma16816(d[1][1], Ah1, Bh[2], Bh[3]);
                // Wh * h_lo
                mma16816(d[0][0], Ah0, Bl[0], Bl[1]);
                mma16816(d[0][1], Ah0, Bl[2], Bl[3]);
                mma16816(d[1][0], Ah1, Bl[0], Bl[1]);
                mma16816(d[1][1], Ah1, Bl[2], Bl[3]);
                // Wl * h_hi
                mma16816(d[0][0], Al0, Bh[0], Bh[1]);
                mma16816(d[0][1], Al0, Bh[2], Bh[3]);
                mma16816(d[1][0], Al1, Bh[0], Bh[1]);
                mma16816(d[1][1], Al1, Bh[2], Bh[3]);
            }
            __syncthreads();
            if (c + 2 < 8) stage_chunk(p, c + 2, sb, tid);
            cp_commit();
        }

        // ---- fragments -> sg[row][b] ----
#pragma unroll
        for (int mt = 0; mt < 2; ++mt)
#pragma unroll
            for (int nt = 0; nt < 2; ++nt) {
                int row0 = mt * 16 + g;
                int col  = w * 16 + nt * 8 + tig * 2;
                *(float2*)&sg[row0 * 66 + col]       = make_float2(d[mt][nt][0], d[mt][nt][1]);
                *(float2*)&sg[(row0 + 8) * 66 + col] = make_float2(d[mt][nt][2], d[mt][nt][3]);
            }
        __syncthreads();

        // ---- WAR: all CTAs must have finished READING buffer (t+1)&1 ----
        if (t && tid == 0)
            while (flag_acq(&g_rdone) < 128u * (unsigned)t) { }
        __syncthreads();

        // ---- activations + state update (4 cells/thread) ----
        float hv[4];
#pragma unroll
        for (int i = 0; i < 4; ++i) {
            int jj = jj0 + i;
            float gi = sg[( 0 + jj) * 66 + ab] + gxr[ 0 + i];
            float gf = sg[( 8 + jj) * 66 + ab] + gxr[ 4 + i];
            float gg = sg[(16 + jj) * 66 + ab] + gxr[ 8 + i];
            float go = sg[(24 + jj) * 66 + ab] + gxr[12 + i];
            float si = 1.f / (1.f + __expf(-gi));
            float sf = 1.f / (1.f + __expf(-gf));
            float so = 1.f / (1.f + __expf(-go));
            cc[i] = sf * cc[i] + si * tanhf(gg);
            hv[i] = so * tanhf(cc[i]);
        }

        // ---- write h^{t+1} bf16 hi/lo ----
        {
            float h0h = __bfloat162float(__float2bfloat16(hv[0]));
            float h1h = __bfloat162float(__float2bfloat16(hv[1]));
            float h2h = __bfloat162float(__float2bfloat16(hv[2]));
            float h3h = __bfloat162float(__float2bfloat16(hv[3]));
            uint2 hi2 = make_uint2(pkbf(hv[0], hv[1]), pkbf(hv[2], hv[3]));
            uint2 lo2 = make_uint2(pkbf(hv[0] - h0h, hv[1] - h1h), pkbf(hv[2] - h2h, hv[3] - h3h));
            int pn = (t + 1) & 1;
            *(uint2*)&g_hbhi[pn][ab][jt * 8 + jj0] = hi2;
            *(uint2*)&g_hblo[pn][ab][jt * 8 + jj0] = lo2;
            if (t == TT - 1)
                *(float4*)(g_hfin + (size_t)ab * HSZ + jt * 8 + jj0) =
                    make_float4(hv[0], hv[1], hv[2], hv[3]);
        }

        __syncthreads();
        if (tid == 0) flag_rel(&g_done);
    }
}

// ---------------------------------------------------------------------------
// Classifier: out[b][o] = g_hfin[b] . W_clf[o] + b_clf[o]
// ---------------------------------------------------------------------------
__global__ __launch_bounds__(128)
void k_classifier(const float* __restrict__ Wclf,
                  const float* __restrict__ bclf,
                  float* __restrict__ out) {
    int b = blockIdx.x;
    int o = threadIdx.x;
    __shared__ float hsh[HSZ];
    for (int k = threadIdx.x; k < HSZ; k += 128) hsh[k] = g_hfin[(size_t)b * HSZ + k];
    __syncthreads();
    const float* wp = Wclf + (size_t)o * HSZ;
    float acc = 0.f;
#pragma unroll 4
    for (int k = 0; k < HSZ; k += 4) {
        float4 wv = *(const float4*)(wp + k);
        acc += wv.x * hsh[k] + wv.y * hsh[k + 1] + wv.z * hsh[k + 2] + wv.w * hsh[k + 3];
    }
    out[b * OSZ + o] = acc + bclf[o];
}

// ---------------------------------------------------------------------------
// Launch (graph-capturable: kernel launches only)
// ---------------------------------------------------------------------------
extern "C" void kernel_launch(void* const* d_in, const int* in_sizes, int n_in,
                              void* d_out, int out_size) {
    const float* x    = (const float*)d_in[0];
    const float* Wih  = (const float*)d_in[1];
    const float* Whh  = (const float*)d_in[2];
    const float* bih  = (const float*)d_in[3];
    const float* bhh  = (const float*)d_in[4];
    const float* Wclf = (const float*)d_in[5];
    const float* bclf = (const float*)d_in[6];
    float* out = (float*)d_out;

    cudaFuncSetAttribute(k_lstm, cudaFuncAttributeMaxDynamicSharedMemorySize, SMEM_TOTAL);

    k_zero<<<256, 256>>>();
    k_input_gemm<<<dim3(256, 32), 256>>>(x, Wih, bih, bhh);
    k_lstm<<<NCTA, NTHR, SMEM_TOTAL>>>(Whh);
    k_classifier<<<64, 128>>>(Wclf, bclf, out);
}

// round 8
// speedup vs baseline: 2.9618x; 1.2486x over previous
#include <cuda_runtime.h>
#include <cuda_fp16.h>
#include <cstdint>
#include <cstddef>

// Problem constants
#define BSZ 64      // batch
#define TT  512     // timesteps
#define ISZ 512     // input size
#define HSZ 1024    // hidden size
#define G4  4096    // 4*HSZ
#define OSZ 128     // output size
#define NCTA 128    // persistent CTAs (1/SM)
#define NTHR 128

typedef unsigned long long u64;

// ---------------------------------------------------------------------------
// Static device scratch
// g_gx: x-gates repacked per-CTA-contiguous: [t][cta][lr][b]  (8KB per CTA/step)
// g_h16: h as fp16, pre-swizzled chunk images: [buf][chunk(8)][b(64)][k(128)]
//        within a chunk: byte = b*256 + (seg ^ (b&7))*16 + inseg, seg = koff>>3
// ---------------------------------------------------------------------------
__device__ __align__(16) float  g_gx[(size_t)TT * G4 * BSZ];
__device__ __align__(16) __half g_h16[2][8 * 64 * 128];
__device__ __align__(16) float  g_hfin[BSZ * HSZ];
__device__ unsigned g_done;    // monotonic: 128*(t+1) when all CTAs published h^{t+1}
__device__ unsigned g_rdone;   // monotonic: 128*(t+1) when all CTAs finished reading h^t

// ---------------------------------------------------------------------------
// Helpers
// ---------------------------------------------------------------------------
__device__ __forceinline__ u64 pk2(float lo, float hi) {
    u64 r; asm("mov.b64 %0, {%1, %2};" : "=l"(r) : "f"(lo), "f"(hi)); return r;
}
__device__ __forceinline__ void fma2(u64& d, u64 a, u64 b) {
    asm("fma.rn.f32x2 %0, %1, %2, %0;" : "+l"(d) : "l"(a), "l"(b));
}
__device__ __forceinline__ float2 upk2(u64 v) {
    float2 r; asm("mov.b64 {%0, %1}, %2;" : "=f"(r.x), "=f"(r.y) : "l"(v)); return r;
}
__device__ __forceinline__ unsigned pkh(float a, float b) {   // low=h(a), high=h(b)
    unsigned r; asm("cvt.rn.f16x2.f32 %0, %1, %2;" : "=r"(r) : "f"(b), "f"(a)); return r;
}
__device__ __forceinline__ unsigned smem_u32(const void* p) {
    unsigned a;
    asm("{ .reg .u64 t; cvta.to.shared.u64 t, %1; cvt.u32.u64 %0, t; }" : "=r"(a) : "l"(p));
    return a;
}
__device__ __forceinline__ void flag_rel(unsigned* f) {
    asm volatile("red.release.gpu.global.add.u32 [%0], %1;" :: "l"(f), "r"(1u) : "memory");
}
__device__ __forceinline__ unsigned flag_acq(const unsigned* f) {
    unsigned v;
    asm volatile("ld.acquire.gpu.global.u32 %0, [%1];" : "=r"(v) : "l"(f) : "memory");
    return v;
}
__device__ __forceinline__ void mbar_init(unsigned a, unsigned cnt) {
    asm volatile("mbarrier.init.shared.b64 [%0], %1;" :: "r"(a), "r"(cnt) : "memory");
}
__device__ __forceinline__ void mbar_expect(unsigned a, unsigned bytes) {
    asm volatile("mbarrier.arrive.expect_tx.shared.b64 _, [%0], %1;" :: "r"(a), "r"(bytes) : "memory");
}
__device__ __forceinline__ void mbar_wait(unsigned a, unsigned parity) {
    asm volatile(
        "{\n\t.reg .pred P;\n\t"
        "WL_%=:\n\t"
        "mbarrier.try_wait.parity.acquire.cta.shared::cta.b64 P, [%0], %1, 0x989680;\n\t"
        "@P bra.uni WD_%=;\n\t"
        "bra.uni WL_%=;\n\t"
        "WD_%=:\n\t}"
        :: "r"(a), "r"(parity) : "memory");
}
__device__ __forceinline__ void bulk_g2s(unsigned sdst, const void* gsrc, unsigned bytes, unsigned mbar) {
    asm volatile("cp.async.bulk.shared::cluster.global.mbarrier::complete_tx::bytes [%0], [%1], %2, [%3];"
                 :: "r"(sdst), "l"(gsrc), "r"(bytes), "r"(mbar) : "memory");
}
// ldmatrix x4 (b16)
__device__ __forceinline__ void ldsm4(unsigned* r, unsigned addr) {
    asm volatile("ldmatrix.sync.aligned.m8n8.x4.shared.b16 {%0,%1,%2,%3}, [%4];"
                 : "=r"(r[0]), "=r"(r[1]), "=r"(r[2]), "=r"(r[3]) : "r"(addr));
}
// mma m16n8k16 row.col f32 += f16*f16
__device__ __forceinline__ void mma16816(float* d, const unsigned* a, unsigned b0, unsigned b1) {
    asm volatile(
        "mma.sync.aligned.m16n8k16.row.col.f32.f16.f16.f32 "
        "{%0,%1,%2,%3}, {%4,%5,%6,%7}, {%8,%9}, {%0,%1,%2,%3};"
        : "+f"(d[0]), "+f"(d[1]), "+f"(d[2]), "+f"(d[3])
        : "r"(a[0]), "r"(a[1]), "r"(a[2]), "r"(a[3]), "r"(b0), "r"(b1));
}

// ---------------------------------------------------------------------------
// Zero h buffer 0 and flags
// ---------------------------------------------------------------------------
__global__ void k_zero() {
    int i = blockIdx.x * blockDim.x + threadIdx.x;
    if (i < 32768) ((unsigned*)&g_h16[0][0])[i] = 0u;    // 65536 halfs
    if (i == 0) { g_done = 0u; g_rdone = 0u; }
}

// ---------------------------------------------------------------------------
// Input GEMM (FFMA2): writes gx repacked [t][cta][lr][b]
// ---------------------------------------------------------------------------
__global__ __launch_bounds__(256, 2)
void k_input_gemm(const float* __restrict__ x,
                  const float* __restrict__ Wih,
                  const float* __restrict__ bih,
                  const float* __restrict__ bhh) {
    const int mt = blockIdx.x;
    const int nt = blockIdx.y;
    __shared__ float As[16][132];
    __shared__ float Bs[16][132];

    const int tid = threadIdx.x;
    const int tx  = tid & 15;
    const int ty  = tid >> 4;
    const int n_base = nt * 128;
    const int m_base = mt * 128;

    u64 acc[8][4];
#pragma unroll
    for (int i = 0; i < 8; ++i)
#pragma unroll
        for (int j = 0; j < 4; ++j) acc[i][j] = 0ULL;

    for (int k0 = 0; k0 < ISZ; k0 += 16) {
#pragma unroll
        for (int it = 0; it < 2; ++it) {
            int f  = it * 256 + tid;
            int r  = f >> 2;
            int kk = (f & 3) << 2;
            float4 v = *(const float4*)(Wih + (size_t)(n_base + r) * ISZ + k0 + kk);
            As[kk + 0][r] = v.x; As[kk + 1][r] = v.y;
            As[kk + 2][r] = v.z; As[kk + 3][r] = v.w;
        }
#pragma unroll
        for (int it = 0; it < 2; ++it) {
            int f  = it * 256 + tid;
            int ml = f >> 2;
            int kk = (f & 3) << 2;
            int m  = m_base + ml;
            int b  = m & 63;
            int t  = m >> 6;
            float4 v = *(const float4*)(x + ((size_t)b * TT + t) * ISZ + k0 + kk);
            Bs[kk + 0][ml] = v.x; Bs[kk + 1][ml] = v.y;
            Bs[kk + 2][ml] = v.z; Bs[kk + 3][ml] = v.w;
        }
        __syncthreads();

#pragma unroll
        for (int k = 0; k < 16; ++k) {
            float a0[4], a1[4];
            *(float4*)a0 = *(const float4*)&As[k][ty * 8];
            *(float4*)a1 = *(const float4*)&As[k][ty * 8 + 4];
            ulonglong2 bp0 = *(const ulonglong2*)&Bs[k][tx * 8];
            ulonglong2 bp1 = *(const ulonglong2*)&Bs[k][tx * 8 + 4];
            u64 bb[4] = {bp0.x, bp0.y, bp1.x, bp1.y};
#pragma unroll
            for (int i = 0; i < 4; ++i) {
                u64 s0 = pk2(a0[i], a0[i]);
                u64 s1 = pk2(a1[i], a1[i]);
#pragma unroll
                for (int j = 0; j < 4; ++j) {
                    fma2(acc[i][j],     s0, bb[j]);
                    fma2(acc[i + 4][j], s1, bb[j]);
                }
            }
        }
        __syncthreads();
    }

    const int m0 = m_base + tx * 8;
    const int b0 = m0 & 63;
    const int t  = m0 >> 6;
#pragma unroll
    for (int i = 0; i < 8; ++i) {
        int n = n_base + ty * 8 + i;
        float bias = bih[n] + bhh[n];
        int gate = n >> 10;
        int j    = n & 1023;
        int rt   = j >> 3;
        int lr   = gate * 8 + (j & 7);
        float o[8];
#pragma unroll
        for (int jj = 0; jj < 4; ++jj) {
            float2 v = upk2(acc[i][jj]);
            o[2 * jj]     = v.x + bias;
            o[2 * jj + 1] = v.y + bias;
        }
        float* dst = g_gx + (((size_t)t * 128 + rt) * 32 + lr) * 64 + b0;
        *(float4*)(dst)     = make_float4(o[0], o[1], o[2], o[3]);
        *(float4*)(dst + 4) = make_float4(o[4], o[5], o[6], o[7]);
    }
}

// ---------------------------------------------------------------------------
// SMEM layout for k_lstm (dynamic, bytes):
//   Whi : 32 rows x (1024 fp16 + 8 pad) stride 2064      [0      , 66048)
//   Wlo : same                                           [66048  , 132096)
//   B   : 4 bufs x 16384 (swizzled chunk images)         [132096 , 197632)
//   gx_s: 32 x 64 f32                                    [197632 , 205824)
//   sg  : 32 x 66 f32                                    [205824 , 214272)
// ---------------------------------------------------------------------------
#define W_STRIDE   2064
#define WLO_OFF    66048
#define B_OFF      132096
#define B_BUFSZ    16384
#define GX_OFF     197632
#define SG_OFF     205824
#define SMEM_TOTAL 214272

// ---------------------------------------------------------------------------
// Persistent tensor-core LSTM (mma.sync f16; W 2-way split, h single fp16).
// CTA jt owns hidden units [8jt,8jt+8) x 4 gates = 32 gate-rows x 64 batch,
// K=1024. W SMEM-resident. h streamed via cp.async.bulk in 8 x 16KB chunks
// (4-deep pipeline). gx via one 8KB bulk per step.
// ---------------------------------------------------------------------------
__global__ __launch_bounds__(NTHR, 1)
void k_lstm(const float* __restrict__ Whh) {
    extern __shared__ __align__(16) char smem[];
    const unsigned sb = smem_u32(smem);
    float* gx_s = (float*)(smem + GX_OFF);
    float* sg   = (float*)(smem + SG_OFF);
    __shared__ __align__(8) u64 s_mbar[5];     // [0..3] B bufs, [4] gx

    const int jt   = blockIdx.x;
    const int tid  = threadIdx.x;
    const int w    = tid >> 5;
    const int lane = tid & 31;

    // ---- one-time: W rows -> SMEM fp16 hi/lo (row lr = gate*8+jj) ----
#pragma unroll
    for (int it = 0; it < 64; ++it) {
        int f   = tid + it * NTHR;         // 8192 float4 total
        int row = f >> 8;                  // 0..31
        int k4  = (f & 255) << 2;          // 0..1020
        int gate = row >> 3, jj = row & 7;
        const float* src = Whh + (size_t)(gate * HSZ + jt * 8 + jj) * HSZ + k4;
        float4 v = *(const float4*)src;
        float xh = __half2float(__float2half_rn(v.x));
        float yh = __half2float(__float2half_rn(v.y));
        float zh = __half2float(__float2half_rn(v.z));
        float wh = __half2float(__float2half_rn(v.w));
        uint2 hi = make_uint2(pkh(v.x, v.y), pkh(v.z, v.w));
        uint2 lo = make_uint2(pkh(v.x - xh, v.y - yh), pkh(v.z - zh, v.w - wh));
        *(uint2*)(smem + (size_t)row * W_STRIDE + k4 * 2)           = hi;
        *(uint2*)(smem + WLO_OFF + (size_t)row * W_STRIDE + k4 * 2) = lo;
    }

    if (tid == 0)
#pragma unroll
        for (int m = 0; m < 5; ++m) mbar_init(smem_u32(&s_mbar[m]), 1);
    __syncthreads();

    unsigned mb[5];
#pragma unroll
    for (int m = 0; m < 5; ++m) mb[m] = smem_u32(&s_mbar[m]);
    unsigned ph[4] = {0u, 0u, 0u, 0u};
    unsigned phgx = 0u;

    // ldmatrix A base (fixed per thread)
    const unsigned aBase = sb + (unsigned)(lane & 15) * W_STRIDE + ((lane >> 4) & 1) * 16u;
    // B addressing: lane -> (batch row, k half), swizzled segs
    const unsigned bRow  = (unsigned)(w * 16 + (lane & 7) + ((lane >> 4) & 1) * 8);
    const unsigned bHalf = (unsigned)((lane >> 3) & 1);
    const unsigned bMask = bRow & 7u;
    const unsigned bRowOff = bRow * 256u;

    // activation mapping: thread -> (jj0 = (tid>>6)*4, b = tid&63)
    const int ab  = tid & 63;
    const int jj0 = (tid >> 6) * 4;
    float cc[4] = {0.f, 0.f, 0.f, 0.f};

    // fragment epilogue positions
    const int fg  = lane >> 2;
    const int tig = lane & 3;

    // producer h-write offset (pre-swizzled chunk image)
    const unsigned hwoff = (unsigned)(jt >> 4) * 16384u + (unsigned)ab * 256u
                         + (unsigned)(((jt & 15) ^ (ab & 7))) * 16u + (unsigned)jj0 * 2u;

    for (int t = 0; t < TT; ++t) {
        const int p = t & 1;

        // ---- tid0: wait h^t published, then launch all bulk copies ----
        if (tid == 0) {
            if (t) while (flag_acq(&g_done) < 128u * (unsigned)t) { }
            const char* hsrc = (const char*)&g_h16[p][0];
#pragma unroll
            for (int c = 0; c < 4; ++c) {
                mbar_expect(mb[c], B_BUFSZ);
                bulk_g2s(sb + B_OFF + (unsigned)c * B_BUFSZ, hsrc + (size_t)c * B_BUFSZ, B_BUFSZ, mb[c]);
            }
            mbar_expect(mb[4], 8192u);
            bulk_g2s(sb + GX_OFF, (const char*)g_gx + ((size_t)t * 128 + jt) * 8192, 8192u, mb[4]);
        }

        float d[2][2][4];
#pragma unroll
        for (int mt = 0; mt < 2; ++mt)
#pragma unroll
            for (int nt = 0; nt < 2; ++nt)
#pragma unroll
                for (int r = 0; r < 4; ++r) d[mt][nt][r] = 0.f;

        for (int c = 0; c < 8; ++c) {
            const int m = c & 3;
            mbar_wait(mb[m], ph[m] & 1u);
            ph[m]++;

            const unsigned ahi  = aBase + (unsigned)c * 256u;
            const unsigned alo  = ahi + WLO_OFF;
            const unsigned bbuf = sb + B_OFF + (unsigned)m * B_BUFSZ + bRowOff;
#pragma unroll
            for (int ks = 0; ks < 8; ++ks) {
                unsigned Ah0[4], Ah1[4], Al0[4], Al1[4], B[4];
                unsigned seg = ((unsigned)(ks * 2) + bHalf) ^ bMask;
                ldsm4(B,   bbuf + (seg << 4));
                ldsm4(Ah0, ahi + ks * 32u);
                ldsm4(Ah1, ahi + ks * 32u + 16u * W_STRIDE);
                ldsm4(Al0, alo + ks * 32u);
                ldsm4(Al1, alo + ks * 32u + 16u * W_STRIDE);
                mma16816(d[0][0], Ah0, B[0], B[1]);
                mma16816(d[0][1], Ah0, B[2], B[3]);
                mma16816(d[1][0], Ah1, B[0], B[1]);
                mma16816(d[1][1], Ah1, B[2], B[3]);
                mma16816(d[0][0], Al0, B[0], B[1]);
                mma16816(d[0][1], Al0, B[2], B[3]);
                mma16816(d[1][0], Al1, B[0], B[1]);
                mma16816(d[1][1], Al1, B[2], B[3]);
            }
            __syncthreads();                       // all reads of buf m done
            if (c + 4 < 8 && tid == 0) {
                const char* hsrc = (const char*)&g_h16[p][0];
                mbar_expect(mb[m], B_BUFSZ);
                bulk_g2s(sb + B_OFF + (unsigned)m * B_BUFSZ, hsrc + (size_t)(c + 4) * B_BUFSZ, B_BUFSZ, mb[m]);
            }
        }
        if (tid == 0) flag_rel(&g_rdone);          // all h^t reads complete

        // ---- fragments -> sg[row][b] ----
#pragma unroll
        for (int mt = 0; mt < 2; ++mt)
#pragma unroll
            for (int nt = 0; nt < 2; ++nt) {
                int row0 = mt * 16 + fg;
                int col  = w * 16 + nt * 8 + tig * 2;
                *(float2*)&sg[row0 * 66 + col]       = make_float2(d[mt][nt][0], d[mt][nt][1]);
                *(float2*)&sg[(row0 + 8) * 66 + col] = make_float2(d[mt][nt][2], d[mt][nt][3]);
            }
        __syncthreads();

        // ---- WAR: all CTAs finished reading buffer (t+1)&1 before we overwrite ----
        if (t && tid == 0)
            while (flag_acq(&g_rdone) < 128u * (unsigned)t) { }
        mbar_wait(mb[4], phgx & 1u);               // gx landed
        phgx++;
        __syncthreads();

        // ---- activations + state update (4 cells/thread) ----
        float hv[4];
#pragma unroll
        for (int i = 0; i < 4; ++i) {
            int jj = jj0 + i;
            float gi = sg[( 0 + jj) * 66 + ab] + gx_s[( 0 + jj) * 64 + ab];
            float gf = sg[( 8 + jj) * 66 + ab] + gx_s[( 8 + jj) * 64 + ab];
            float gg = sg[(16 + jj) * 66 + ab] + gx_s[(16 + jj) * 64 + ab];
            float go = sg[(24 + jj) * 66 + ab] + gx_s[(24 + jj) * 64 + ab];
            float si = 1.f / (1.f + __expf(-gi));
            float sf = 1.f / (1.f + __expf(-gf));
            float so = 1.f / (1.f + __expf(-go));
            cc[i] = sf * cc[i] + si * tanhf(gg);
            hv[i] = so * tanhf(cc[i]);
        }

        // ---- write h^{t+1} fp16 into swizzled chunk image ----
        {
            uint2 h4 = make_uint2(pkh(hv[0], hv[1]), pkh(hv[2], hv[3]));
            *(uint2*)((char*)&g_h16[(t + 1) & 1][0] + hwoff) = h4;
            if (t == TT - 1)
                *(float4*)(g_hfin + (size_t)ab * HSZ + jt * 8 + jj0) =
                    make_float4(hv[0], hv[1], hv[2], hv[3]);
        }

        __syncthreads();
        if (tid == 0) flag_rel(&g_done);
    }
}

// ---------------------------------------------------------------------------
// Classifier: out[b][o] = g_hfin[b] . W_clf[o] + b_clf[o]
// ---------------------------------------------------------------------------
__global__ __launch_bounds__(128)
void k_classifier(const float* __restrict__ Wclf,
                  const float* __restrict__ bclf,
                  float* __restrict__ out) {
    int b = blockIdx.x;
    int o = threadIdx.x;
    __shared__ float hsh[HSZ];
    for (int k = threadIdx.x; k < HSZ; k += 128) hsh[k] = g_hfin[(size_t)b * HSZ + k];
    __syncthreads();
    const float* wp = Wclf + (size_t)o * HSZ;
    float acc = 0.f;
#pragma unroll 4
    for (int k = 0; k < HSZ; k += 4) {
        float4 wv = *(const float4*)(wp + k);
        acc += wv.x * hsh[k] + wv.y * hsh[k + 1] + wv.z * hsh[k + 2] + wv.w * hsh[k + 3];
    }
    out[b * OSZ + o] = acc + bclf[o];
}

// ---------------------------------------------------------------------------
// Launch (graph-capturable: kernel launches only)
// ---------------------------------------------------------------------------
extern "C" void kernel_launch(void* const* d_in, const int* in_sizes, int n_in,
                              void* d_out, int out_size) {
    const float* x    = (const float*)d_in[0];
    const float* Wih  = (const float*)d_in[1];
    const float* Whh  = (const float*)d_in[2];
    const float* bih  = (const float*)d_in[3];
    const float* bhh  = (const float*)d_in[4];
    const float* Wclf = (const float*)d_in[5];
    const float* bclf = (const float*)d_in[6];
    float* out = (float*)d_out;

    cudaFuncSetAttribute(k_lstm, cudaFuncAttributeMaxDynamicSharedMemorySize, SMEM_TOTAL);

    k_zero<<<256, 256>>>();
    k_input_gemm<<<dim3(256, 32), 256>>>(x, Wih, bih, bhh);
    k_lstm<<<NCTA, NTHR, SMEM_TOTAL>>>(Whh);
    k_classifier<<<64, 128>>>(Wclf, bclf, out);
}

// round 9
// speedup vs baseline: 2.9624x; 1.0002x over previous
#include <cuda_runtime.h>
#include <cuda_fp16.h>
#include <cstdint>
#include <cstddef>

// Problem constants
#define BSZ 64
#define TT  512
#define ISZ 512
#define HSZ 1024
#define G4  4096
#define OSZ 128
#define NCTA 128
#define NTHR 128

typedef unsigned long long u64;

// ---------------------------------------------------------------------------
// Static device scratch
// g_gx   : x-gates repacked [t][rt(128)][lr(32)][b(64)] f32
// g_h16  : h fp16, pre-swizzled chunk images [buf][chunk(8)][b(64)][k(128)]
// g_x16* : x fp16 hi/lo, block images [mt(256)*8+kc][m(128)][k(64)] swizzled
// g_w16* : W_ih fp16 hi/lo, block images [nt(32)*8+kc][n(128)][k(64)] swizzled
// ---------------------------------------------------------------------------
__device__ __align__(16) float  g_gx[(size_t)TT * G4 * BSZ];
__device__ __align__(16) __half g_h16[2][8 * 64 * 128];
__device__ __align__(16) __half g_x16hi[(size_t)2048 * 8192];
__device__ __align__(16) __half g_x16lo[(size_t)2048 * 8192];
__device__ __align__(16) __half g_w16hi[(size_t)256 * 8192];
__device__ __align__(16) __half g_w16lo[(size_t)256 * 8192];
__device__ __align__(16) float  g_hfin[BSZ * HSZ];
__device__ unsigned g_donec[8];    // per-chunk h-publish counters (16/chunk/step)
__device__ unsigned g_rdonec[8];   // per-chunk h-copy-done counters (128/chunk/step)

// ---------------------------------------------------------------------------
// Helpers
// ---------------------------------------------------------------------------
__device__ __forceinline__ u64 pk2(float lo, float hi) {
    u64 r; asm("mov.b64 %0, {%1, %2};" : "=l"(r) : "f"(lo), "f"(hi)); return r;
}
__device__ __forceinline__ float2 upk2(u64 v) {
    float2 r; asm("mov.b64 {%0, %1}, %2;" : "=f"(r.x), "=f"(r.y) : "l"(v)); return r;
}
__device__ __forceinline__ unsigned pkh(float a, float b) {   // low=h(a), high=h(b)
    unsigned r; asm("cvt.rn.f16x2.f32 %0, %1, %2;" : "=r"(r) : "f"(b), "f"(a)); return r;
}
__device__ __forceinline__ unsigned smem_u32(const void* p) {
    unsigned a;
    asm("{ .reg .u64 t; cvta.to.shared.u64 t, %1; cvt.u32.u64 %0, t; }" : "=r"(a) : "l"(p));
    return a;
}
__device__ __forceinline__ void flag_rel(unsigned* f) {
    asm volatile("red.release.gpu.global.add.u32 [%0], %1;" :: "l"(f), "r"(1u) : "memory");
}
__device__ __forceinline__ unsigned flag_acq(const unsigned* f) {
    unsigned v;
    asm volatile("ld.acquire.gpu.global.u32 %0, [%1];" : "=r"(v) : "l"(f) : "memory");
    return v;
}
__device__ __forceinline__ void mbar_init(unsigned a, unsigned cnt) {
    asm volatile("mbarrier.init.shared.b64 [%0], %1;" :: "r"(a), "r"(cnt) : "memory");
}
__device__ __forceinline__ void mbar_expect(unsigned a, unsigned bytes) {
    asm volatile("mbarrier.arrive.expect_tx.shared.b64 _, [%0], %1;" :: "r"(a), "r"(bytes) : "memory");
}
__device__ __forceinline__ void mbar_wait(unsigned a, unsigned parity) {
    asm volatile(
        "{\n\t.reg .pred P;\n\t"
        "WL_%=:\n\t"
        "mbarrier.try_wait.parity.acquire.cta.shared::cta.b64 P, [%0], %1, 0x989680;\n\t"
        "@P bra.uni WD_%=;\n\t"
        "bra.uni WL_%=;\n\t"
        "WD_%=:\n\t}"
        :: "r"(a), "r"(parity) : "memory");
}
__device__ __forceinline__ void bulk_g2s(unsigned sdst, const void* gsrc, unsigned bytes, unsigned mbar) {
    asm volatile("cp.async.bulk.shared::cluster.global.mbarrier::complete_tx::bytes [%0], [%1], %2, [%3];"
                 :: "r"(sdst), "l"(gsrc), "r"(bytes), "r"(mbar) : "memory");
}
__device__ __forceinline__ void ldsm4(unsigned* r, unsigned addr) {
    asm volatile("ldmatrix.sync.aligned.m8n8.x4.shared.b16 {%0,%1,%2,%3}, [%4];"
                 : "=r"(r[0]), "=r"(r[1]), "=r"(r[2]), "=r"(r[3]) : "r"(addr));
}
__device__ __forceinline__ void mma16816(float* d, const unsigned* a, unsigned b0, unsigned b1) {
    asm volatile(
        "mma.sync.aligned.m16n8k16.row.col.f32.f16.f16.f32 "
        "{%0,%1,%2,%3}, {%4,%5,%6,%7}, {%8,%9}, {%0,%1,%2,%3};"
        : "+f"(d[0]), "+f"(d[1]), "+f"(d[2]), "+f"(d[3])
        : "r"(a[0]), "r"(a[1]), "r"(a[2]), "r"(a[3]), "r"(b0), "r"(b1));
}

// ---------------------------------------------------------------------------
// Zero h buffer 0 and flags
// ---------------------------------------------------------------------------
__global__ void k_zero() {
    int i = blockIdx.x * blockDim.x + threadIdx.x;
    if (i < 32768) ((unsigned*)&g_h16[0][0])[i] = 0u;
    if (i < 8) { g_donec[i] = 0u; g_rdonec[i] = 0u; }
}

// ---------------------------------------------------------------------------
// Prep: convert x and W_ih to fp16 hi/lo block images (swizzled for ldmatrix)
// seg count: x = 32768 m-rows * 64 segs; W = 4096 rows * 64 segs
// ---------------------------------------------------------------------------
#define NXSEG (32768 * 64)
#define NWSEG (4096 * 64)
__global__ __launch_bounds__(256)
void k_prep(const float* __restrict__ x, const float* __restrict__ Wih) {
    int s0 = blockIdx.x * blockDim.x + threadIdx.x;
    const int stride = gridDim.x * blockDim.x;
    for (int s = s0; s < NXSEG + NWSEG; s += stride) {
        const float* src;
        char *dhi, *dlo;
        unsigned off;
        if (s < NXSEG) {
            int m  = s >> 6;
            int sk = s & 63;
            int b = m & 63, t = m >> 6;
            src = x + ((size_t)b * TT + t) * ISZ + sk * 8;
            int mt = m >> 7, ml = m & 127, kc = sk >> 3, seg = sk & 7;
            off = (unsigned)(mt * 8 + kc) * 16384u + (unsigned)ml * 128u
                + (unsigned)((seg ^ (ml & 7)) * 16);
            dhi = (char*)g_x16hi; dlo = (char*)g_x16lo;
        } else {
            int sw = s - NXSEG;
            int n  = sw >> 6;
            int sk = sw & 63;
            src = Wih + (size_t)n * ISZ + sk * 8;
            int nt = n >> 7, nl = n & 127, kc = sk >> 3, seg = sk & 7;
            off = (unsigned)(nt * 8 + kc) * 16384u + (unsigned)nl * 128u
                + (unsigned)((seg ^ (nl & 7)) * 16);
            dhi = (char*)g_w16hi; dlo = (char*)g_w16lo;
        }
        float4 v0 = *(const float4*)(src);
        float4 v1 = *(const float4*)(src + 4);
        uint4 hi = make_uint4(pkh(v0.x, v0.y), pkh(v0.z, v0.w),
                              pkh(v1.x, v1.y), pkh(v1.z, v1.w));
        float ax = __half2float(__float2half_rn(v0.x));
        float ay = __half2float(__float2half_rn(v0.y));
        float az = __half2float(__float2half_rn(v0.z));
        float aw = __half2float(__float2half_rn(v0.w));
        float bx = __half2float(__float2half_rn(v1.x));
        float by = __half2float(__float2half_rn(v1.y));
        float bz = __half2float(__float2half_rn(v1.z));
        float bw = __half2float(__float2half_rn(v1.w));
        uint4 lo = make_uint4(pkh(v0.x - ax, v0.y - ay), pkh(v0.z - az, v0.w - aw),
                              pkh(v1.x - bx, v1.y - by), pkh(v1.z - bz, v1.w - bw));
        *(uint4*)(dhi + off) = hi;
        *(uint4*)(dlo + off) = lo;
    }
}

// ---------------------------------------------------------------------------
// Input GEMM via mma.sync fp16 (3-product split, ~fp32-exact).
// CTA tile: 128 gate-rows (nt) x 128 bt (mt), K=512 in 8 chunks of 64,
// double-buffered bulk copies. 8 warps: warp = 32 gates x 64 bt.
// Writes gx repacked [t][rt][lr][b] + bias.
// SMEM: stage(2) x { Ahi 16K | Alo 16K | Bhi 16K | Blo 16K } + bias 512B
// ---------------------------------------------------------------------------
#define IG_SMEM (2 * 65536 + 512)
__global__ __launch_bounds__(256, 1)
void k_input_mma(const float* __restrict__ bih, const float* __restrict__ bhh) {
    extern __shared__ __align__(16) char smem[];
    const unsigned sb = smem_u32(smem);
    float* sbias = (float*)(smem + 131072);
    __shared__ __align__(8) u64 s_mbar[2];

    const int nt = blockIdx.x;    // 0..31
    const int mt = blockIdx.y;    // 0..255
    const int tid  = threadIdx.x;
    const int w    = tid >> 5;
    const int lane = tid & 31;
    const int wgate = (w >> 1) * 32;
    const int wm    = (w & 1) * 64;

    if (tid < 128) {
        int n = nt * 128 + tid;
        sbias[tid] = bih[n] + bhh[n];
    }
    if (tid == 0) { mbar_init(smem_u32(&s_mbar[0]), 1); mbar_init(smem_u32(&s_mbar[1]), 1); }
    __syncthreads();
    unsigned mb[2] = { smem_u32(&s_mbar[0]), smem_u32(&s_mbar[1]) };
    unsigned ph[2] = {0u, 0u};

    auto issue = [&](int kc) {
        int st = kc & 1;
        unsigned base = sb + (unsigned)st * 65536u;
        size_t woff = ((size_t)nt * 8 + kc) * 16384;
        size_t xoff = ((size_t)mt * 8 + kc) * 16384;
        mbar_expect(mb[st], 65536u);
        bulk_g2s(base,          (const char*)g_w16hi + woff, 16384u, mb[st]);
        bulk_g2s(base + 16384u, (const char*)g_w16lo + woff, 16384u, mb[st]);
        bulk_g2s(base + 32768u, (const char*)g_x16hi + xoff, 16384u, mb[st]);
        bulk_g2s(base + 49152u, (const char*)g_x16lo + xoff, 16384u, mb[st]);
    };
    if (tid == 0) { issue(0); issue(1); }

    float d[2][8][4];
#pragma unroll
    for (int i = 0; i < 2; ++i)
#pragma unroll
        for (int j = 0; j < 8; ++j)
#pragma unroll
            for (int r = 0; r < 4; ++r) d[i][j][r] = 0.f;

    // fixed per-thread ldmatrix row offsets
    const int rA0 = wgate + (lane & 15);
    const int rA1 = rA0 + 16;
    const unsigned aSegSel = (unsigned)((lane >> 4) & 1);
    const int rBbase = wm + (lane & 7) + ((lane >> 4) & 1) * 8;
    const unsigned bSegSel = (unsigned)((lane >> 3) & 1);

    for (int kc = 0; kc < 8; ++kc) {
        const int st = kc & 1;
        mbar_wait(mb[st], ph[st] & 1u);
        ph[st]++;
        unsigned base = sb + (unsigned)st * 65536u;
        unsigned Ahi = base, Alo = base + 16384u, Bhi = base + 32768u, Blo = base + 49152u;
#pragma unroll
        for (int ks = 0; ks < 4; ++ks) {
            unsigned Ah0[4], Ah1[4], Al0[4], Al1[4];
            unsigned segA0 = ((unsigned)(ks * 2) + aSegSel);
            ldsm4(Ah0, Ahi + (unsigned)rA0 * 128u + ((segA0 ^ (unsigned)(rA0 & 7)) << 4));
            ldsm4(Ah1, Ahi + (unsigned)rA1 * 128u + ((segA0 ^ (unsigned)(rA1 & 7)) << 4));
            ldsm4(Al0, Alo + (unsigned)rA0 * 128u + ((segA0 ^ (unsigned)(rA0 & 7)) << 4));
            ldsm4(Al1, Alo + (unsigned)rA1 * 128u + ((segA0 ^ (unsigned)(rA1 & 7)) << 4));
#pragma unroll
            for (int np = 0; np < 4; ++np) {
                int rB = rBbase + np * 16;
                unsigned segB = ((unsigned)(ks * 2) + bSegSel) ^ (unsigned)(rB & 7);
                unsigned Bh[4], Bl[4];
                ldsm4(Bh, Bhi + (unsigned)rB * 128u + (segB << 4));
                ldsm4(Bl, Blo + (unsigned)rB * 128u + (segB << 4));
                mma16816(d[0][np * 2],     Ah0, Bh[0], Bh[1]);
                mma16816(d[0][np * 2 + 1], Ah0, Bh[2], Bh[3]);
                mma16816(d[1][np * 2],     Ah1, Bh[0], Bh[1]);
                mma16816(d[1][np * 2 + 1], Ah1, Bh[2], Bh[3]);
                mma16816(d[0][np * 2],     Ah0, Bl[0], Bl[1]);
                mma16816(d[0][np * 2 + 1], Ah0, Bl[2], Bl[3]);
                mma16816(d[1][np * 2],     Ah1, Bl[0], Bl[1]);
                mma16816(d[1][np * 2 + 1], Ah1, Bl[2], Bl[3]);
                mma16816(d[0][np * 2],     Al0, Bh[0], Bh[1]);
                mma16816(d[0][np * 2 + 1], Al0, Bh[2], Bh[3]);
                mma16816(d[1][np * 2],     Al1, Bh[0], Bh[1]);
                mma16816(d[1][np * 2 + 1], Al1, Bh[2], Bh[3]);
            }
        }
        __syncthreads();
        if (kc + 2 < 8 && tid == 0) issue(kc + 2);
    }

    // epilogue: add bias, write gx [t][rt][lr][b]
    const int fg  = lane >> 2;
    const int tig = lane & 3;
#pragma unroll
    for (int mt2 = 0; mt2 < 2; ++mt2) {
        int row = wgate + mt2 * 16 + fg;
        int n1 = nt * 128 + row;
        int n2 = n1 + 8;
        int g1 = n1 >> 10, j1 = n1 & 1023;
        int g2 = n2 >> 10, j2 = n2 & 1023;
        int rl1 = (j1 >> 3) * 32 + g1 * 8 + (j1 & 7);
        int rl2 = (j2 >> 3) * 32 + g2 * 8 + (j2 & 7);
        float b1 = sbias[row], b2 = sbias[row + 8];
#pragma unroll
        for (int np2 = 0; np2 < 8; ++np2) {
            int mcol = wm + (np2 >> 1) * 16 + (np2 & 1) * 8 + tig * 2;
            int tt = mt * 2 + (mcol >> 6);
            int bb = mcol & 63;
            *(float2*)(g_gx + ((size_t)tt * 4096 + rl1) * 64 + bb) =
                make_float2(d[mt2][np2][0] + b1, d[mt2][np2][1] + b1);
            *(float2*)(g_gx + ((size_t)tt * 4096 + rl2) * 64 + bb) =
                make_float2(d[mt2][np2][2] + b2, d[mt2][np2][3] + b2);
        }
    }
}

// ---------------------------------------------------------------------------
// SMEM layout for k_lstm (bytes):
//   Whi : 32 x (1024 fp16 + 8 pad) stride 2064           [0      , 66048)
//   Wlo : same                                           [66048  , 132096)
//   B   : 4 bufs x 16384 (swizzled chunk images)         [132096 , 197632)
//   gx_s: 32 x 64 f32                                    [197632 , 205824)
//   sg  : 32 x 66 f32                                    [205824 , 214272)
// ---------------------------------------------------------------------------
#define W_STRIDE   2064
#define WLO_OFF    66048
#define B_OFF      132096
#define B_BUFSZ    16384
#define GX_OFF     197632
#define SG_OFF     205824
#define SMEM_TOTAL 214272

// ---------------------------------------------------------------------------
// Persistent tensor-core LSTM (mma.sync f16; W 2-split, h fp16).
// Per-chunk publish/read flags for fine-grained cross-CTA pipelining.
// ---------------------------------------------------------------------------
__global__ __launch_bounds__(NTHR, 1)
void k_lstm(const float* __restrict__ Whh) {
    extern __shared__ __align__(16) char smem[];
    const unsigned sb = smem_u32(smem);
    float* gx_s = (float*)(smem + GX_OFF);
    float* sg   = (float*)(smem + SG_OFF);
    __shared__ __align__(8) u64 s_mbar[5];

    const int jt   = blockIdx.x;
    const int tid  = threadIdx.x;
    const int w    = tid >> 5;
    const int lane = tid & 31;
    const int kw   = jt >> 4;            // chunk this CTA produces into

    // ---- one-time: W rows -> SMEM fp16 hi/lo (row lr = gate*8+jj) ----
#pragma unroll
    for (int it = 0; it < 64; ++it) {
        int f   = tid + it * NTHR;
        int row = f >> 8;
        int k4  = (f & 255) << 2;
        int gate = row >> 3, jj = row & 7;
        const float* src = Whh + (size_t)(gate * HSZ + jt * 8 + jj) * HSZ + k4;
        float4 v = *(const float4*)src;
        float xh = __half2float(__float2half_rn(v.x));
        float yh = __half2float(__float2half_rn(v.y));
        float zh = __half2float(__float2half_rn(v.z));
        float wh = __half2float(__float2half_rn(v.w));
        uint2 hi = make_uint2(pkh(v.x, v.y), pkh(v.z, v.w));
        uint2 lo = make_uint2(pkh(v.x - xh, v.y - yh), pkh(v.z - zh, v.w - wh));
        *(uint2*)(smem + (size_t)row * W_STRIDE + k4 * 2)           = hi;
        *(uint2*)(smem + WLO_OFF + (size_t)row * W_STRIDE + k4 * 2) = lo;
    }

    if (tid == 0)
#pragma unroll
        for (int m = 0; m < 5; ++m) mbar_init(smem_u32(&s_mbar[m]), 1);
    __syncthreads();

    unsigned mb[5];
#pragma unroll
    for (int m = 0; m < 5; ++m) mb[m] = smem_u32(&s_mbar[m]);
    unsigned ph[4] = {0u, 0u, 0u, 0u};
    unsigned phgx = 0u;

    const unsigned aBase = sb + (unsigned)(lane & 15) * W_STRIDE + ((lane >> 4) & 1) * 16u;
    const unsigned bRow  = (unsigned)(w * 16 + (lane & 7) + ((lane >> 4) & 1) * 8);
    const unsigned bHalf = (unsigned)((lane >> 3) & 1);
    const unsigned bMask = bRow & 7u;
    const unsigned bRowOff = bRow * 256u;

    const int ab  = tid & 63;
    const int jj0 = (tid >> 6) * 4;
    float cc[4] = {0.f, 0.f, 0.f, 0.f};

    const int fg  = lane >> 2;
    const int tig = lane & 3;

    const unsigned hwoff = (unsigned)kw * 16384u + (unsigned)ab * 256u
                         + (unsigned)(((jt & 15) ^ (ab & 7))) * 16u + (unsigned)jj0 * 2u;

    for (int t = 0; t < TT; ++t) {
        const int p = t & 1;

        // ---- tid0: gx bulk, then per-chunk wait+issue for first 4 chunks ----
        if (tid == 0) {
            mbar_expect(mb[4], 8192u);
            bulk_g2s(sb + GX_OFF, (const char*)g_gx + ((size_t)t * 128 + jt) * 8192, 8192u, mb[4]);
            const char* hsrc = (const char*)&g_h16[p][0];
            unsigned tgt = 16u * (unsigned)t;
#pragma unroll
            for (int c = 0; c < 4; ++c) {
                if (t) while (flag_acq(&g_donec[c]) < tgt) { }
                mbar_expect(mb[c], B_BUFSZ);
                bulk_g2s(sb + B_OFF + (unsigned)c * B_BUFSZ, hsrc + (size_t)c * B_BUFSZ, B_BUFSZ, mb[c]);
            }
        }

        float d[2][2][4];
#pragma unroll
        for (int mt = 0; mt < 2; ++mt)
#pragma unroll
            for (int nt2 = 0; nt2 < 2; ++nt2)
#pragma unroll
                for (int r = 0; r < 4; ++r) d[mt][nt2][r] = 0.f;

        for (int c = 0; c < 8; ++c) {
            const int m = c & 3;
            mbar_wait(mb[m], ph[m] & 1u);
            ph[m]++;
            if (tid == 0) flag_rel(&g_rdonec[c]);   // copy landed -> global WAR released

            const unsigned ahi  = aBase + (unsigned)c * 256u;
            const unsigned alo  = ahi + WLO_OFF;
            const unsigned bbuf = sb + B_OFF + (unsigned)m * B_BUFSZ + bRowOff;
#pragma unroll
            for (int ks = 0; ks < 8; ++ks) {
                unsigned Ah0[4], Ah1[4], Al0[4], Al1[4], B[4];
                unsigned seg = ((unsigned)(ks * 2) + bHalf) ^ bMask;
                ldsm4(B,   bbuf + (seg << 4));
                ldsm4(Ah0, ahi + ks * 32u);
                ldsm4(Ah1, ahi + ks * 32u + 16u * W_STRIDE);
                ldsm4(Al0, alo + ks * 32u);
                ldsm4(Al1, alo + ks * 32u + 16u * W_STRIDE);
                mma16816(d[0][0], Ah0, B[0], B[1]);
                mma16816(d[0][1], Ah0, B[2], B[3]);
                mma16816(d[1][0], Ah1, B[0], B[1]);
                mma16816(d[1][1], Ah1, B[2], B[3]);
                mma16816(d[0][0], Al0, B[0], B[1]);
                mma16816(d[0][1], Al0, B[2], B[3]);
                mma16816(d[1][0], Al1, B[0], B[1]);
                mma16816(d[1][1], Al1, B[2], B[3]);
            }
            __syncthreads();                       // all SMEM reads of buf m done
            if (c + 4 < 8 && tid == 0) {
                if (t) while (flag_acq(&g_donec[c + 4]) < 16u * (unsigned)t) { }
                const char* hsrc = (const char*)&g_h16[p][0];
                mbar_expect(mb[m], B_BUFSZ);
                bulk_g2s(sb + B_OFF + (unsigned)m * B_BUFSZ, hsrc + (size_t)(c + 4) * B_BUFSZ, B_BUFSZ, mb[m]);
            }
        }

        // ---- fragments -> sg[row][b] ----
#pragma unroll
        for (int mt = 0; mt < 2; ++mt)
#pragma unroll
            for (int nt2 = 0; nt2 < 2; ++nt2) {
                int row0 = mt * 16 + fg;
                int col  = w * 16 + nt2 * 8 + tig * 2;
                *(float2*)&sg[row0 * 66 + col]       = make_float2(d[mt][nt2][0], d[mt][nt2][1]);
                *(float2*)&sg[(row0 + 8) * 66 + col] = make_float2(d[mt][nt2][2], d[mt][nt2][3]);
            }
        __syncthreads();

        // ---- WAR: all CTAs copied our chunk of buffer (t+1)&1 at step t-1 ----
        if (t && tid == 0)
            while (flag_acq(&g_rdonec[kw]) < 128u * (unsigned)t) { }
        mbar_wait(mb[4], phgx & 1u);
        phgx++;
        __syncthreads();

        // ---- activations + state update (4 cells/thread) ----
        float hv[4];
#pragma unroll
        for (int i = 0; i < 4; ++i) {
            int jj = jj0 + i;
            float gi = sg[( 0 + jj) * 66 + ab] + gx_s[( 0 + jj) * 64 + ab];
            float gf = sg[( 8 + jj) * 66 + ab] + gx_s[( 8 + jj) * 64 + ab];
            float gg = sg[(16 + jj) * 66 + ab] + gx_s[(16 + jj) * 64 + ab];
            float go = sg[(24 + jj) * 66 + ab] + gx_s[(24 + jj) * 64 + ab];
            float si = 1.f / (1.f + __expf(-gi));
            float sf = 1.f / (1.f + __expf(-gf));
            float so = 1.f / (1.f + __expf(-go));
            cc[i] = sf * cc[i] + si * tanhf(gg);
            hv[i] = so * tanhf(cc[i]);
        }

        // ---- write h^{t+1} fp16 into swizzled chunk image ----
        {
            uint2 h4 = make_uint2(pkh(hv[0], hv[1]), pkh(hv[2], hv[3]));
            *(uint2*)((char*)&g_h16[(t + 1) & 1][0] + hwoff) = h4;
            if (t == TT - 1)
                *(float4*)(g_hfin + (size_t)ab * HSZ + jt * 8 + jj0) =
                    make_float4(hv[0], hv[1], hv[2], hv[3]);
        }

        __syncthreads();
        if (tid == 0) flag_rel(&g_donec[kw]);
    }
}

// ---------------------------------------------------------------------------
// Classifier
// ---------------------------------------------------------------------------
__global__ __launch_bounds__(128)
void k_classifier(const float* __restrict__ Wclf,
                  const float* __restrict__ bclf,
                  float* __restrict__ out) {
    int b = blockIdx.x;
    int o = threadIdx.x;
    __shared__ float hsh[HSZ];
    for (int k = threadIdx.x; k < HSZ; k += 128) hsh[k] = g_hfin[(size_t)b * HSZ + k];
    __syncthreads();
    const float* wp = Wclf + (size_t)o * HSZ;
    float acc = 0.f;
#pragma unroll 4
    for (int k = 0; k < HSZ; k += 4) {
        float4 wv = *(const float4*)(wp + k);
        acc += wv.x * hsh[k] + wv.y * hsh[k + 1] + wv.z * hsh[k + 2] + wv.w * hsh[k + 3];
    }
    out[b * OSZ + o] = acc + bclf[o];
}

// ---------------------------------------------------------------------------
// Launch (graph-capturable: kernel launches only)
// ---------------------------------------------------------------------------
extern "C" void kernel_launch(void* const* d_in, const int* in_sizes, int n_in,
                              void* d_out, int out_size) {
    const float* x    = (const float*)d_in[0];
    const float* Wih  = (const float*)d_in[1];
    const float* Whh  = (const float*)d_in[2];
    const float* bih  = (const float*)d_in[3];
    const float* bhh  = (const float*)d_in[4];
    const float* Wclf = (const float*)d_in[5];
    const float* bclf = (const float*)d_in[6];
    float* out = (float*)d_out;

    cudaFuncSetAttribute(k_input_mma, cudaFuncAttributeMaxDynamicSharedMemorySize, IG_SMEM);
    cudaFuncSetAttribute(k_lstm,      cudaFuncAttributeMaxDynamicSharedMemorySize, SMEM_TOTAL);

    k_zero<<<256, 256>>>();
    k_prep<<<2304, 256>>>(x, Wih);
    k_input_mma<<<dim3(32, 256), 256, IG_SMEM>>>(bih, bhh);
    k_lstm<<<NCTA, NTHR, SMEM_TOTAL>>>(Whh);
    k_classifier<<<64, 128>>>(Wclf, bclf, out);
}

// round 10
// speedup vs baseline: 5.0090x; 1.6909x over previous
#include <cuda_runtime.h>
#include <cuda_fp16.h>
#include <cstdint>
#include <cstddef>

// Problem constants
#define BSZ 64
#define TT  512
#define ISZ 512
#define HSZ 1024
#define G4  4096
#define OSZ 128
#define NCTA 128
#define NTHR 128

typedef unsigned long long u64;

// ---------------------------------------------------------------------------
// Static device scratch
// g_gx   : x-gates repacked [t][rt(128)][lr(32)][b(64)] f32
// g_h16  : h fp16, pre-swizzled chunk images [buf][chunk(8)][b(64)][k(128)]
// g_x16hi: x fp16 block images [mt(256)*8+kc][m(128)][k(64)] swizzled
// g_w16* : W_ih fp16 hi/lo block images [nt(32)*8+kc][n(128)][k(64)] swizzled
// ---------------------------------------------------------------------------
__device__ __align__(16) float  g_gx[(size_t)TT * G4 * BSZ];
__device__ __align__(16) __half g_h16[2][8 * 64 * 128];
__device__ __align__(16) __half g_x16hi[(size_t)2048 * 8192];
__device__ __align__(16) __half g_w16hi[(size_t)256 * 8192];
__device__ __align__(16) __half g_w16lo[(size_t)256 * 8192];
__device__ __align__(16) float  g_hfin[BSZ * HSZ];
__device__ unsigned g_donec[8];    // per-chunk h-publish counters (16/chunk/step)

// ---------------------------------------------------------------------------
// Helpers
// ---------------------------------------------------------------------------
__device__ __forceinline__ unsigned pkh(float a, float b) {   // low=h(a), high=h(b)
    unsigned r; asm("cvt.rn.f16x2.f32 %0, %1, %2;" : "=r"(r) : "f"(b), "f"(a)); return r;
}
__device__ __forceinline__ unsigned smem_u32(const void* p) {
    unsigned a;
    asm("{ .reg .u64 t; cvta.to.shared.u64 t, %1; cvt.u32.u64 %0, t; }" : "=r"(a) : "l"(p));
    return a;
}
__device__ __forceinline__ void flag_rel(unsigned* f) {
    asm volatile("red.release.gpu.global.add.u32 [%0], %1;" :: "l"(f), "r"(1u) : "memory");
}
__device__ __forceinline__ unsigned flag_acq(const unsigned* f) {
    unsigned v;
    asm volatile("ld.acquire.gpu.global.u32 %0, [%1];" : "=r"(v) : "l"(f) : "memory");
    return v;
}
__device__ __forceinline__ void mbar_init(unsigned a, unsigned cnt) {
    asm volatile("mbarrier.init.shared.b64 [%0], %1;" :: "r"(a), "r"(cnt) : "memory");
}
__device__ __forceinline__ void mbar_expect(unsigned a, unsigned bytes) {
    asm volatile("mbarrier.arrive.expect_tx.shared.b64 _, [%0], %1;" :: "r"(a), "r"(bytes) : "memory");
}
__device__ __forceinline__ void mbar_wait(unsigned a, unsigned parity) {
    asm volatile(
        "{\n\t.reg .pred P;\n\t"
        "WL_%=:\n\t"
        "mbarrier.try_wait.parity.acquire.cta.shared::cta.b64 P, [%0], %1, 0x989680;\n\t"
        "@P bra.uni WD_%=;\n\t"
        "bra.uni WL_%=;\n\t"
        "WD_%=:\n\t}"
        :: "r"(a), "r"(parity) : "memory");
}
__device__ __forceinline__ void bulk_g2s(unsigned sdst, const void* gsrc, unsigned bytes, unsigned mbar) {
    asm volatile("cp.async.bulk.shared::cluster.global.mbarrier::complete_tx::bytes [%0], [%1], %2, [%3];"
                 :: "r"(sdst), "l"(gsrc), "r"(bytes), "r"(mbar) : "memory");
}
__device__ __forceinline__ void ldsm4(unsigned* r, unsigned addr) {
    asm volatile("ldmatrix.sync.aligned.m8n8.x4.shared.b16 {%0,%1,%2,%3}, [%4];"
                 : "=r"(r[0]), "=r"(r[1]), "=r"(r[2]), "=r"(r[3]) : "r"(addr));
}
__device__ __forceinline__ void mma16816(float* d, const unsigned* a, unsigned b0, unsigned b1) {
    asm volatile(
        "mma.sync.aligned.m16n8k16.row.col.f32.f16.f16.f32 "
        "{%0,%1,%2,%3}, {%4,%5,%6,%7}, {%8,%9}, {%0,%1,%2,%3};"
        : "+f"(d[0]), "+f"(d[1]), "+f"(d[2]), "+f"(d[3])
        : "r"(a[0]), "r"(a[1]), "r"(a[2]), "r"(a[3]), "r"(b0), "r"(b1));
}

// ---------------------------------------------------------------------------
// Zero h buffer 0 and flags
// ---------------------------------------------------------------------------
__global__ void k_zero() {
    int i = blockIdx.x * blockDim.x + threadIdx.x;
    if (i < 32768) ((unsigned*)&g_h16[0][0])[i] = 0u;
    if (i < 8) g_donec[i] = 0u;
}

// ---------------------------------------------------------------------------
// Prep: x -> fp16 hi block images; W_ih -> fp16 hi/lo block images (swizzled)
// ---------------------------------------------------------------------------
#define NXSEG (32768 * 64)
#define NWSEG (4096 * 64)
__global__ __launch_bounds__(256)
void k_prep(const float* __restrict__ x, const float* __restrict__ Wih) {
    int s0 = blockIdx.x * blockDim.x + threadIdx.x;
    const int stride = gridDim.x * blockDim.x;
    for (int s = s0; s < NXSEG + NWSEG; s += stride) {
        if (s < NXSEG) {
            int m  = s >> 6;
            int sk = s & 63;
            int b = m & 63, t = m >> 6;
            const float* src = x + ((size_t)b * TT + t) * ISZ + sk * 8;
            int mt = m >> 7, ml = m & 127, kc = sk >> 3, seg = sk & 7;
            unsigned off = (unsigned)(mt * 8 + kc) * 16384u + (unsigned)ml * 128u
                         + (unsigned)((seg ^ (ml & 7)) * 16);
            float4 v0 = *(const float4*)(src);
            float4 v1 = *(const float4*)(src + 4);
            uint4 hi = make_uint4(pkh(v0.x, v0.y), pkh(v0.z, v0.w),
                                  pkh(v1.x, v1.y), pkh(v1.z, v1.w));
            *(uint4*)((char*)g_x16hi + off) = hi;
        } else {
            int sw = s - NXSEG;
            int n  = sw >> 6;
            int sk = sw & 63;
            const float* src = Wih + (size_t)n * ISZ + sk * 8;
            int nt = n >> 7, nl = n & 127, kc = sk >> 3, seg = sk & 7;
            unsigned off = (unsigned)(nt * 8 + kc) * 16384u + (unsigned)nl * 128u
                         + (unsigned)((seg ^ (nl & 7)) * 16);
            float4 v0 = *(const float4*)(src);
            float4 v1 = *(const float4*)(src + 4);
            uint4 hi = make_uint4(pkh(v0.x, v0.y), pkh(v0.z, v0.w),
                                  pkh(v1.x, v1.y), pkh(v1.z, v1.w));
            float ax = __half2float(__float2half_rn(v0.x));
            float ay = __half2float(__float2half_rn(v0.y));
            float az = __half2float(__float2half_rn(v0.z));
            float aw = __half2float(__float2half_rn(v0.w));
            float bx = __half2float(__float2half_rn(v1.x));
            float by = __half2float(__float2half_rn(v1.y));
            float bz = __half2float(__float2half_rn(v1.z));
            float bw = __half2float(__float2half_rn(v1.w));
            uint4 lo = make_uint4(pkh(v0.x - ax, v0.y - ay), pkh(v0.z - az, v0.w - aw),
                                  pkh(v1.x - bx, v1.y - by), pkh(v1.z - bz, v1.w - bw));
            *(uint4*)((char*)g_w16hi + off) = hi;
            *(uint4*)((char*)g_w16lo + off) = lo;
        }
    }
}

// ---------------------------------------------------------------------------
// Input GEMM via mma.sync fp16, 2-product split (Whi*xhi + Wlo*xhi).
// CTA tile: 128 gates (nt) x 128 bt (mt), K=512 in 8 chunks of 64.
// SMEM: stage(2) x { Ahi 16K | Alo 16K | Bhi 16K } + bias 512B
// ---------------------------------------------------------------------------
#define IG_STAGE  49152
#define IG_SMEM  (2 * IG_STAGE + 512)
__global__ __launch_bounds__(256, 1)
void k_input_mma(const float* __restrict__ bih, const float* __restrict__ bhh) {
    extern __shared__ __align__(16) char smem[];
    const unsigned sb = smem_u32(smem);
    float* sbias = (float*)(smem + 2 * IG_STAGE);
    __shared__ __align__(8) u64 s_mbar[2];

    const int nt = blockIdx.x;    // 0..31
    const int mt = blockIdx.y;    // 0..255
    const int tid  = threadIdx.x;
    const int w    = tid >> 5;
    const int lane = tid & 31;
    const int wgate = (w >> 1) * 32;
    const int wm    = (w & 1) * 64;

    if (tid < 128) {
        int n = nt * 128 + tid;
        sbias[tid] = bih[n] + bhh[n];
    }
    if (tid == 0) { mbar_init(smem_u32(&s_mbar[0]), 1); mbar_init(smem_u32(&s_mbar[1]), 1); }
    __syncthreads();
    unsigned mb[2] = { smem_u32(&s_mbar[0]), smem_u32(&s_mbar[1]) };
    unsigned ph[2] = {0u, 0u};

    auto issue = [&](int kc) {
        int st = kc & 1;
        unsigned base = sb + (unsigned)st * IG_STAGE;
        size_t woff = ((size_t)nt * 8 + kc) * 16384;
        size_t xoff = ((size_t)mt * 8 + kc) * 16384;
        mbar_expect(mb[st], IG_STAGE);
        bulk_g2s(base,          (const char*)g_w16hi + woff, 16384u, mb[st]);
        bulk_g2s(base + 16384u, (const char*)g_w16lo + woff, 16384u, mb[st]);
        bulk_g2s(base + 32768u, (const char*)g_x16hi + xoff, 16384u, mb[st]);
    };
    if (tid == 0) { issue(0); issue(1); }

    float d[2][8][4];
#pragma unroll
    for (int i = 0; i < 2; ++i)
#pragma unroll
        for (int j = 0; j < 8; ++j)
#pragma unroll
            for (int r = 0; r < 4; ++r) d[i][j][r] = 0.f;

    const int rA0 = wgate + (lane & 15);
    const int rA1 = rA0 + 16;
    const unsigned aSegSel = (unsigned)((lane >> 4) & 1);
    const int rBbase = wm + (lane & 7) + ((lane >> 4) & 1) * 8;
    const unsigned bSegSel = (unsigned)((lane >> 3) & 1);

    for (int kc = 0; kc < 8; ++kc) {
        const int st = kc & 1;
        mbar_wait(mb[st], ph[st] & 1u);
        ph[st]++;
        unsigned base = sb + (unsigned)st * IG_STAGE;
        unsigned Ahi = base, Alo = base + 16384u, Bhi = base + 32768u;
#pragma unroll
        for (int ks = 0; ks < 4; ++ks) {
            unsigned Ah0[4], Ah1[4], Al0[4], Al1[4];
            unsigned segA0 = ((unsigned)(ks * 2) + aSegSel);
            ldsm4(Ah0, Ahi + (unsigned)rA0 * 128u + ((segA0 ^ (unsigned)(rA0 & 7)) << 4));
            ldsm4(Ah1, Ahi + (unsigned)rA1 * 128u + ((segA0 ^ (unsigned)(rA1 & 7)) << 4));
            ldsm4(Al0, Alo + (unsigned)rA0 * 128u + ((segA0 ^ (unsigned)(rA0 & 7)) << 4));
            ldsm4(Al1, Alo + (unsigned)rA1 * 128u + ((segA0 ^ (unsigned)(rA1 & 7)) << 4));
#pragma unroll
            for (int np = 0; np < 4; ++np) {
                int rB = rBbase + np * 16;
                unsigned segB = ((unsigned)(ks * 2) + bSegSel) ^ (unsigned)(rB & 7);
                unsigned Bh[4];
                ldsm4(Bh, Bhi + (unsigned)rB * 128u + (segB << 4));
                mma16816(d[0][np * 2],     Ah0, Bh[0], Bh[1]);
                mma16816(d[0][np * 2 + 1], Ah0, Bh[2], Bh[3]);
                mma16816(d[1][np * 2],     Ah1, Bh[0], Bh[1]);
                mma16816(d[1][np * 2 + 1], Ah1, Bh[2], Bh[3]);
                mma16816(d[0][np * 2],     Al0, Bh[0], Bh[1]);
                mma16816(d[0][np * 2 + 1], Al0, Bh[2], Bh[3]);
                mma16816(d[1][np * 2],     Al1, Bh[0], Bh[1]);
                mma16816(d[1][np * 2 + 1], Al1, Bh[2], Bh[3]);
            }
        }
        __syncthreads();
        if (kc + 2 < 8 && tid == 0) issue(kc + 2);
    }

    const int fg  = lane >> 2;
    const int tig = lane & 3;
#pragma unroll
    for (int mt2 = 0; mt2 < 2; ++mt2) {
        int row = wgate + mt2 * 16 + fg;
        int n1 = nt * 128 + row;
        int n2 = n1 + 8;
        int g1 = n1 >> 10, j1 = n1 & 1023;
        int g2 = n2 >> 10, j2 = n2 & 1023;
        int rl1 = (j1 >> 3) * 32 + g1 * 8 + (j1 & 7);
        int rl2 = (j2 >> 3) * 32 + g2 * 8 + (j2 & 7);
        float b1 = sbias[row], b2 = sbias[row + 8];
#pragma unroll
        for (int np2 = 0; np2 < 8; ++np2) {
            int mcol = wm + (np2 >> 1) * 16 + (np2 & 1) * 8 + tig * 2;
            int tt = mt * 2 + (mcol >> 6);
            int bb = mcol & 63;
            *(float2*)(g_gx + ((size_t)tt * 4096 + rl1) * 64 + bb) =
                make_float2(d[mt2][np2][0] + b1, d[mt2][np2][1] + b1);
            *(float2*)(g_gx + ((size_t)tt * 4096 + rl2) * 64 + bb) =
                make_float2(d[mt2][np2][2] + b2, d[mt2][np2][3] + b2);
        }
    }
}

// ---------------------------------------------------------------------------
// SMEM layout for k_lstm (bytes):
//   W   : 32 x (1024 fp16 + 8 pad) stride 2064           [0      , 66048)
//   B   : 8 bufs x 16384 (swizzled chunk images)         [66048  , 197120)
//   gx_s: 32 x 64 f32                                    [197120 , 205312)
//   sg  : 32 x 66 f32                                    [205312 , 213760)
// ---------------------------------------------------------------------------
#define W_STRIDE   2064
#define B_OFF      66048
#define B_BUFSZ    16384
#define GX_OFF     197120
#define SG_OFF     205312
#define SMEM_TOTAL 213760

// ---------------------------------------------------------------------------
// Persistent tensor-core LSTM. Single fp16 W (h and W both fp16-quantized).
// 8 single-use h buffers; all copies issued at step start gated on per-chunk
// publish flags. NO WAR flag: publishing h^t proves reads of h^{t-1} done,
// so donec[*] >= 16t observed by every writer makes double-buffering safe.
// ---------------------------------------------------------------------------
__global__ __launch_bounds__(NTHR, 1)
void k_lstm(const float* __restrict__ Whh) {
    extern __shared__ __align__(16) char smem[];
    const unsigned sb = smem_u32(smem);
    float* gx_s = (float*)(smem + GX_OFF);
    float* sg   = (float*)(smem + SG_OFF);
    __shared__ __align__(8) u64 s_mbar[9];     // [0..7] B chunks, [8] gx

    const int jt   = blockIdx.x;
    const int tid  = threadIdx.x;
    const int w    = tid >> 5;
    const int lane = tid & 31;
    const int kw   = jt >> 4;            // chunk this CTA produces into

    // ---- one-time: W rows -> SMEM fp16 (row lr = gate*8+jj) ----
#pragma unroll
    for (int it = 0; it < 64; ++it) {
        int f   = tid + it * NTHR;
        int row = f >> 8;
        int k4  = (f & 255) << 2;
        int gate = row >> 3, jj = row & 7;
        const float* src = Whh + (size_t)(gate * HSZ + jt * 8 + jj) * HSZ + k4;
        float4 v = *(const float4*)src;
        uint2 hi = make_uint2(pkh(v.x, v.y), pkh(v.z, v.w));
        *(uint2*)(smem + (size_t)row * W_STRIDE + k4 * 2) = hi;
    }

    if (tid == 0)
#pragma unroll
        for (int m = 0; m < 9; ++m) mbar_init(smem_u32(&s_mbar[m]), 1);
    __syncthreads();

    unsigned mb[9];
#pragma unroll
    for (int m = 0; m < 9; ++m) mb[m] = smem_u32(&s_mbar[m]);

    const unsigned aBase = sb + (unsigned)(lane & 15) * W_STRIDE + ((lane >> 4) & 1) * 16u;
    const unsigned bRow  = (unsigned)(w * 16 + (lane & 7) + ((lane >> 4) & 1) * 8);
    const unsigned bHalf = (unsigned)((lane >> 3) & 1);
    const unsigned bMask = bRow & 7u;
    const unsigned bRowOff = bRow * 256u;

    const int ab  = tid & 63;
    const int jj0 = (tid >> 6) * 4;
    float cc[4] = {0.f, 0.f, 0.f, 0.f};

    const int fg  = lane >> 2;
    const int tig = lane & 3;

    const unsigned hwoff = (unsigned)kw * 16384u + (unsigned)ab * 256u
                         + (unsigned)(((jt & 15) ^ (ab & 7))) * 16u + (unsigned)jj0 * 2u;

    for (int t = 0; t < TT; ++t) {
        const int p = t & 1;
        const unsigned par = (unsigned)(t & 1);

        // ---- tid0: gx bulk + all 8 chunk copies (each gated on publish flag) ----
        if (tid == 0) {
            mbar_expect(mb[8], 8192u);
            bulk_g2s(sb + GX_OFF, (const char*)g_gx + ((size_t)t * 128 + jt) * 8192, 8192u, mb[8]);
            const char* hsrc = (const char*)&g_h16[p][0];
            unsigned tgt = 16u * (unsigned)t;
#pragma unroll
            for (int c = 0; c < 8; ++c) {
                if (t) while (flag_acq(&g_donec[c]) < tgt) { }
                mbar_expect(mb[c], B_BUFSZ);
                bulk_g2s(sb + B_OFF + (unsigned)c * B_BUFSZ, hsrc + (size_t)c * B_BUFSZ, B_BUFSZ, mb[c]);
            }
        }

        float d[2][2][4];
#pragma unroll
        for (int mt = 0; mt < 2; ++mt)
#pragma unroll
            for (int nt2 = 0; nt2 < 2; ++nt2)
#pragma unroll
                for (int r = 0; r < 4; ++r) d[mt][nt2][r] = 0.f;

        for (int c = 0; c < 8; ++c) {
            mbar_wait(mb[c], par);
            const unsigned ahi  = aBase + (unsigned)c * 256u;
            const unsigned bbuf = sb + B_OFF + (unsigned)c * B_BUFSZ + bRowOff;
#pragma unroll
            for (int ks = 0; ks < 8; ++ks) {
                unsigned Ah0[4], Ah1[4], B[4];
                unsigned seg = ((unsigned)(ks * 2) + bHalf) ^ bMask;
                ldsm4(B,   bbuf + (seg << 4));
                ldsm4(Ah0, ahi + ks * 32u);
                ldsm4(Ah1, ahi + ks * 32u + 16u * W_STRIDE);
                mma16816(d[0][0], Ah0, B[0], B[1]);
                mma16816(d[0][1], Ah0, B[2], B[3]);
                mma16816(d[1][0], Ah1, B[0], B[1]);
                mma16816(d[1][1], Ah1, B[2], B[3]);
            }
        }

        // ---- fragments -> sg[row][b] ----
#pragma unroll
        for (int mt = 0; mt < 2; ++mt)
#pragma unroll
            for (int nt2 = 0; nt2 < 2; ++nt2) {
                int row0 = mt * 16 + fg;
                int col  = w * 16 + nt2 * 8 + tig * 2;
                *(float2*)&sg[row0 * 66 + col]       = make_float2(d[mt][nt2][0], d[mt][nt2][1]);
                *(float2*)&sg[(row0 + 8) * 66 + col] = make_float2(d[mt][nt2][2], d[mt][nt2][3]);
            }
        mbar_wait(mb[8], par);               // gx landed
        __syncthreads();

        // ---- activations + state update (4 cells/thread) ----
        float hv[4];
#pragma unroll
        for (int i = 0; i < 4; ++i) {
            int jj = jj0 + i;
            float gi = sg[( 0 + jj) * 66 + ab] + gx_s[( 0 + jj) * 64 + ab];
            float gf = sg[( 8 + jj) * 66 + ab] + gx_s[( 8 + jj) * 64 + ab];
            float gg = sg[(16 + jj) * 66 + ab] + gx_s[(16 + jj) * 64 + ab];
            float go = sg[(24 + jj) * 66 + ab] + gx_s[(24 + jj) * 64 + ab];
            float si = 1.f / (1.f + __expf(-gi));
            float sf = 1.f / (1.f + __expf(-gf));
            float so = 1.f / (1.f + __expf(-go));
            cc[i] = sf * cc[i] + si * tanhf(gg);
            hv[i] = so * tanhf(cc[i]);
        }

        // ---- write h^{t+1} fp16 into swizzled chunk image ----
        {
            uint2 h4 = make_uint2(pkh(hv[0], hv[1]), pkh(hv[2], hv[3]));
            *(uint2*)((char*)&g_h16[(t + 1) & 1][0] + hwoff) = h4;
            if (t == TT - 1)
                *(float4*)(g_hfin + (size_t)ab * HSZ + jt * 8 + jj0) =
                    make_float4(hv[0], hv[1], hv[2], hv[3]);
        }

        __syncthreads();
        if (tid == 0) flag_rel(&g_donec[kw]);
    }
}

// ---------------------------------------------------------------------------
// Classifier
// ---------------------------------------------------------------------------
__global__ __launch_bounds__(128)
void k_classifier(const float* __restrict__ Wclf,
                  const float* __restrict__ bclf,
                  float* __restrict__ out) {
    int b = blockIdx.x;
    int o = threadIdx.x;
    __shared__ float hsh[HSZ];
    for (int k = threadIdx.x; k < HSZ; k += 128) hsh[k] = g_hfin[(size_t)b * HSZ + k];
    __syncthreads();
    const float* wp = Wclf + (size_t)o * HSZ;
    float acc = 0.f;
#pragma unroll 4
    for (int k = 0; k < HSZ; k += 4) {
        float4 wv = *(const float4*)(wp + k);
        acc += wv.x * hsh[k] + wv.y * hsh[k + 1] + wv.z * hsh[k + 2] + wv.w * hsh[k + 3];
    }
    out[b * OSZ + o] = acc + bclf[o];
}

// ---------------------------------------------------------------------------
// Launch (graph-capturable: kernel launches only)
// ---------------------------------------------------------------------------
extern "C" void kernel_launch(void* const* d_in, const int* in_sizes, int n_in,
                              void* d_out, int out_size) {
    const float* x    = (const float*)d_in[0];
    const float* Wih  = (const float*)d_in[1];
    const float* Whh  = (const float*)d_in[2];
    const float* bih  = (const float*)d_in[3];
    const float* bhh  = (const float*)d_in[4];
    const float* Wclf = (const float*)d_in[5];
    const float* bclf = (const float*)d_in[6];
    float* out = (float*)d_out;

    cudaFuncSetAttribute(k_input_mma, cudaFuncAttributeMaxDynamicSharedMemorySize, IG_SMEM);
    cudaFuncSetAttribute(k_lstm,      cudaFuncAttributeMaxDynamicSharedMemorySize, SMEM_TOTAL);

    k_zero<<<256, 256>>>();
    k_prep<<<2304, 256>>>(x, Wih);
    k_input_mma<<<dim3(32, 256), 256, IG_SMEM>>>(bih, bhh);
    k_lstm<<<NCTA, NTHR, SMEM_TOTAL>>>(Whh);
    k_classifier<<<64, 128>>>(Wclf, bclf, out);
}

// round 11
// speedup vs baseline: 6.0703x; 1.2119x over previous
#include <cuda_runtime.h>
#include <cuda_fp16.h>
#include <cstdint>
#include <cstddef>

// Problem constants
#define BSZ 64
#define TT  512
#define ISZ 512
#define HSZ 1024
#define G4  4096
#define OSZ 128
#define NCTA 128
#define NTHR 128

typedef unsigned long long u64;

// ---------------------------------------------------------------------------
// Static device scratch
// g_gxf : x-gates in FRAGMENT order: [t][jt][gate(4)][nt(2)][slot(128)] float2
//         slot = w*32 + jj*4 + tig ; .x/.y = batch e 0/1
// g_h16 : h fp16, pre-swizzled chunk images [buf][chunk(8)][b(64)][k(128)]
// g_x16 : x fp16 block images [mt(256)*8+kc][m(128)][k(64)] swizzled
// g_w16 : W_ih fp16 block images [nt(32)*8+kc][n(128)][k(64)] swizzled
// ---------------------------------------------------------------------------
__device__ __align__(16) float  g_gxf[(size_t)TT * 128 * 4 * 2 * 128 * 2];
__device__ __align__(16) __half g_h16[2][8 * 64 * 128];
__device__ __align__(16) __half g_x16[(size_t)2048 * 8192];
__device__ __align__(16) __half g_w16[(size_t)256 * 8192];
__device__ __align__(16) float  g_hfin[BSZ * HSZ];
__device__ unsigned g_donec[8];    // per-chunk publish counters (64/chunk/step)

// ---------------------------------------------------------------------------
// Helpers
// ---------------------------------------------------------------------------
__device__ __forceinline__ unsigned pkh(float a, float b) {   // low=h(a), high=h(b)
    unsigned r; asm("cvt.rn.f16x2.f32 %0, %1, %2;" : "=r"(r) : "f"(b), "f"(a)); return r;
}
__device__ __forceinline__ unsigned smem_u32(const void* p) {
    unsigned a;
    asm("{ .reg .u64 t; cvta.to.shared.u64 t, %1; cvt.u32.u64 %0, t; }" : "=r"(a) : "l"(p));
    return a;
}
__device__ __forceinline__ void flag_rel(unsigned* f) {
    asm volatile("red.release.gpu.global.add.u32 [%0], %1;" :: "l"(f), "r"(1u) : "memory");
}
__device__ __forceinline__ unsigned flag_acq(const unsigned* f) {
    unsigned v;
    asm volatile("ld.acquire.gpu.global.u32 %0, [%1];" : "=r"(v) : "l"(f) : "memory");
    return v;
}
__device__ __forceinline__ void mbar_init(unsigned a, unsigned cnt) {
    asm volatile("mbarrier.init.shared.b64 [%0], %1;" :: "r"(a), "r"(cnt) : "memory");
}
__device__ __forceinline__ void mbar_expect(unsigned a, unsigned bytes) {
    asm volatile("mbarrier.arrive.expect_tx.shared.b64 _, [%0], %1;" :: "r"(a), "r"(bytes) : "memory");
}
__device__ __forceinline__ void mbar_wait(unsigned a, unsigned parity) {
    asm volatile(
        "{\n\t.reg .pred P;\n\t"
        "WL_%=:\n\t"
        "mbarrier.try_wait.parity.acquire.cta.shared::cta.b64 P, [%0], %1, 0x989680;\n\t"
        "@P bra.uni WD_%=;\n\t"
        "bra.uni WL_%=;\n\t"
        "WD_%=:\n\t}"
        :: "r"(a), "r"(parity) : "memory");
}
__device__ __forceinline__ void bulk_g2s(unsigned sdst, const void* gsrc, unsigned bytes, unsigned mbar) {
    asm volatile("cp.async.bulk.shared::cluster.global.mbarrier::complete_tx::bytes [%0], [%1], %2, [%3];"
                 :: "r"(sdst), "l"(gsrc), "r"(bytes), "r"(mbar) : "memory");
}
__device__ __forceinline__ void ldsm4(unsigned* r, unsigned addr) {
    asm volatile("ldmatrix.sync.aligned.m8n8.x4.shared.b16 {%0,%1,%2,%3}, [%4];"
                 : "=r"(r[0]), "=r"(r[1]), "=r"(r[2]), "=r"(r[3]) : "r"(addr));
}
__device__ __forceinline__ void mma16816(float* d, const unsigned* a, unsigned b0, unsigned b1) {
    asm volatile(
        "mma.sync.aligned.m16n8k16.row.col.f32.f16.f16.f32 "
        "{%0,%1,%2,%3}, {%4,%5,%6,%7}, {%8,%9}, {%0,%1,%2,%3};"
        : "+f"(d[0]), "+f"(d[1]), "+f"(d[2]), "+f"(d[3])
        : "r"(a[0]), "r"(a[1]), "r"(a[2]), "r"(a[3]), "r"(b0), "r"(b1));
}
__device__ __forceinline__ float sigm(float x) { return 1.f / (1.f + __expf(-x)); }
__device__ __forceinline__ float tanh_fast(float x) {
    float e = __expf(2.f * x);
    return 1.f - 2.f / (e + 1.f);
}

// ---------------------------------------------------------------------------
// Zero h buffer 0 and flags
// ---------------------------------------------------------------------------
__global__ void k_zero() {
    int i = blockIdx.x * blockDim.x + threadIdx.x;
    if (i < 32768) ((unsigned*)&g_h16[0][0])[i] = 0u;
    if (i < 8) g_donec[i] = 0u;
}

// ---------------------------------------------------------------------------
// Prep: x -> fp16 block images; W_ih -> fp16 block images (swizzled)
// ---------------------------------------------------------------------------
#define NXSEG (32768 * 64)
#define NWSEG (4096 * 64)
__global__ __launch_bounds__(256)
void k_prep(const float* __restrict__ x, const float* __restrict__ Wih) {
    int s0 = blockIdx.x * blockDim.x + threadIdx.x;
    const int stride = gridDim.x * blockDim.x;
    for (int s = s0; s < NXSEG + NWSEG; s += stride) {
        const float* src;
        char* dst;
        unsigned off;
        if (s < NXSEG) {
            int m  = s >> 6;
            int sk = s & 63;
            int b = m & 63, t = m >> 6;
            src = x + ((size_t)b * TT + t) * ISZ + sk * 8;
            int mt = m >> 7, ml = m & 127, kc = sk >> 3, seg = sk & 7;
            off = (unsigned)(mt * 8 + kc) * 16384u + (unsigned)ml * 128u
                + (unsigned)((seg ^ (ml & 7)) * 16);
            dst = (char*)g_x16;
        } else {
            int sw = s - NXSEG;
            int n  = sw >> 6;
            int sk = sw & 63;
            src = Wih + (size_t)n * ISZ + sk * 8;
            int nt = n >> 7, nl = n & 127, kc = sk >> 3, seg = sk & 7;
            off = (unsigned)(nt * 8 + kc) * 16384u + (unsigned)nl * 128u
                + (unsigned)((seg ^ (nl & 7)) * 16);
            dst = (char*)g_w16;
        }
        float4 v0 = *(const float4*)(src);
        float4 v1 = *(const float4*)(src + 4);
        uint4 hi = make_uint4(pkh(v0.x, v0.y), pkh(v0.z, v0.w),
                              pkh(v1.x, v1.y), pkh(v1.z, v1.w));
        *(uint4*)(dst + off) = hi;
    }
}

// ---------------------------------------------------------------------------
// Input GEMM via mma.sync fp16 (single product).
// CTA tile: 128 gates (nt) x 128 bt (mt), K=512 in 8 chunks of 64.
// Writes gx in fragment order (g_gxf) + bias.
// SMEM: stage(2) x { W 16K | X 16K } + bias 512B
// ---------------------------------------------------------------------------
#define IG_STAGE  32768
#define IG_SMEM  (2 * IG_STAGE + 512)
__global__ __launch_bounds__(256, 2)
void k_input_mma(const float* __restrict__ bih, const float* __restrict__ bhh) {
    extern __shared__ __align__(16) char smem[];
    const unsigned sb = smem_u32(smem);
    float* sbias = (float*)(smem + 2 * IG_STAGE);
    __shared__ __align__(8) u64 s_mbar[2];

    const int nt = blockIdx.x;    // 0..31
    const int mt = blockIdx.y;    // 0..255
    const int tid  = threadIdx.x;
    const int w    = tid >> 5;
    const int lane = tid & 31;
    const int wgate = (w >> 1) * 32;
    const int wm    = (w & 1) * 64;

    if (tid < 128) {
        int n = nt * 128 + tid;
        sbias[tid] = bih[n] + bhh[n];
    }
    if (tid == 0) { mbar_init(smem_u32(&s_mbar[0]), 1); mbar_init(smem_u32(&s_mbar[1]), 1); }
    __syncthreads();
    unsigned mb[2] = { smem_u32(&s_mbar[0]), smem_u32(&s_mbar[1]) };
    unsigned ph[2] = {0u, 0u};

    auto issue = [&](int kc) {
        int st = kc & 1;
        unsigned base = sb + (unsigned)st * IG_STAGE;
        size_t woff = ((size_t)nt * 8 + kc) * 16384;
        size_t xoff = ((size_t)mt * 8 + kc) * 16384;
        mbar_expect(mb[st], IG_STAGE);
        bulk_g2s(base,          (const char*)g_w16 + woff, 16384u, mb[st]);
        bulk_g2s(base + 16384u, (const char*)g_x16 + xoff, 16384u, mb[st]);
    };
    if (tid == 0) { issue(0); issue(1); }

    float d[2][8][4];
#pragma unroll
    for (int i = 0; i < 2; ++i)
#pragma unroll
        for (int j = 0; j < 8; ++j)
#pragma unroll
            for (int r = 0; r < 4; ++r) d[i][j][r] = 0.f;

    const int rA0 = wgate + (lane & 15);
    const int rA1 = rA0 + 16;
    const unsigned aSegSel = (unsigned)((lane >> 4) & 1);
    const int rBbase = wm + (lane & 7) + ((lane >> 4) & 1) * 8;
    const unsigned bSegSel = (unsigned)((lane >> 3) & 1);

    for (int kc = 0; kc < 8; ++kc) {
        const int st = kc & 1;
        mbar_wait(mb[st], ph[st] & 1u);
        ph[st]++;
        unsigned base = sb + (unsigned)st * IG_STAGE;
        unsigned Aim = base, Bim = base + 16384u;
#pragma unroll
        for (int ks = 0; ks < 4; ++ks) {
            unsigned Ah0[4], Ah1[4];
            unsigned segA0 = ((unsigned)(ks * 2) + aSegSel);
            ldsm4(Ah0, Aim + (unsigned)rA0 * 128u + ((segA0 ^ (unsigned)(rA0 & 7)) << 4));
            ldsm4(Ah1, Aim + (unsigned)rA1 * 128u + ((segA0 ^ (unsigned)(rA1 & 7)) << 4));
#pragma unroll
            for (int np = 0; np < 4; ++np) {
                int rB = rBbase + np * 16;
                unsigned segB = ((unsigned)(ks * 2) + bSegSel) ^ (unsigned)(rB & 7);
                unsigned Bh[4];
                ldsm4(Bh, Bim + (unsigned)rB * 128u + (segB << 4));
                mma16816(d[0][np * 2],     Ah0, Bh[0], Bh[1]);
                mma16816(d[0][np * 2 + 1], Ah0, Bh[2], Bh[3]);
                mma16816(d[1][np * 2],     Ah1, Bh[0], Bh[1]);
                mma16816(d[1][np * 2 + 1], Ah1, Bh[2], Bh[3]);
            }
        }
        __syncthreads();
        if (kc + 2 < 8 && tid == 0) issue(kc + 2);
    }

    // epilogue: write gx in fragment order
    const int fg  = lane >> 2;
    const int tig = lane & 3;
#pragma unroll
    for (int mt2 = 0; mt2 < 2; ++mt2) {
#pragma unroll
        for (int rr = 0; rr < 2; ++rr) {         // rr=0 -> regs{0,1}, rr=1 -> regs{2,3} (+8 rows)
            int row = wgate + mt2 * 16 + fg + rr * 8;
            int n = nt * 128 + row;
            int gate = n >> 10, jseq = n & 1023;
            int jtv = jseq >> 3, jj = jseq & 7;
            float bias = sbias[row];
#pragma unroll
            for (int j = 0; j < 8; ++j) {
                int mcol = wm + (j >> 1) * 16 + (j & 1) * 8 + tig * 2;
                int tt = mt * 2 + (mcol >> 6);
                int bb = mcol & 63;
                int w_t = bb >> 4, nt_t = (bb >> 3) & 1, tig_t = (bb >> 1) & 3;
                size_t idx = ((((size_t)tt * 128 + jtv) * 4 + gate) * 2 + nt_t) * 128
                           + (w_t * 32 + jj * 4 + tig_t);
                ((float2*)g_gxf)[idx] = make_float2(d[mt2][j][rr * 2] + bias,
                                                    d[mt2][j][rr * 2 + 1] + bias);
            }
        }
    }
}

// ---------------------------------------------------------------------------
// SMEM layout for k_lstm (bytes):
//   W : 32 x (1024 fp16 + 8 pad) stride 2064             [0     , 66048)
//   B : 8 bufs x 16384 (swizzled chunk images)           [66048 , 197120)
// ---------------------------------------------------------------------------
#define W_STRIDE   2064
#define B_OFF      66048
#define B_BUFSZ    16384
#define SMEM_TOTAL 197120

// ---------------------------------------------------------------------------
// Persistent tensor-core LSTM. Register-resident epilogue:
// fragment thread (warp w, lane) owns all 4 gates of jj=lane>>2 for 4 batch
// cols -> activations in registers, h stored as 4 fp16, per-warp publish.
// Chunk copies issued by lane0 of each warp (parallel flag waits).
// ---------------------------------------------------------------------------
__global__ __launch_bounds__(NTHR, 1)
void k_lstm(const float* __restrict__ Whh) {
    extern __shared__ __align__(16) char smem[];
    const unsigned sb = smem_u32(smem);
    __shared__ __align__(8) u64 s_mbar[8];

    const int jt   = blockIdx.x;
    const int tid  = threadIdx.x;
    const int w    = tid >> 5;
    const int lane = tid & 31;
    const int kw   = jt >> 4;            // chunk this CTA produces into

    // ---- one-time: W_hh rows -> SMEM fp16 (row lr = gate*8+jj) ----
#pragma unroll
    for (int it = 0; it < 64; ++it) {
        int f   = tid + it * NTHR;
        int row = f >> 8;
        int k4  = (f & 255) << 2;
        int gate = row >> 3, jj = row & 7;
        const float* src = Whh + (size_t)(gate * HSZ + jt * 8 + jj) * HSZ + k4;
        float4 v = *(const float4*)src;
        uint2 hi = make_uint2(pkh(v.x, v.y), pkh(v.z, v.w));
        *(uint2*)(smem + (size_t)row * W_STRIDE + k4 * 2) = hi;
    }

    if (tid == 0)
#pragma unroll
        for (int m = 0; m < 8; ++m) mbar_init(smem_u32(&s_mbar[m]), 1);
    __syncthreads();

    unsigned mb[8];
#pragma unroll
    for (int m = 0; m < 8; ++m) mb[m] = smem_u32(&s_mbar[m]);

    const unsigned aBase = sb + (unsigned)(lane & 15) * W_STRIDE + ((lane >> 4) & 1) * 16u;
    const unsigned bRow  = (unsigned)(w * 16 + (lane & 7) + ((lane >> 4) & 1) * 8);
    const unsigned bHalf = (unsigned)((lane >> 3) & 1);
    const unsigned bMask = bRow & 7u;
    const unsigned bRowOff = bRow * 256u;

    const int fg  = lane >> 2;           // jj owned by this thread
    const int tig = lane & 3;
    float cc[4] = {0.f, 0.f, 0.f, 0.f};  // cells: [nt*2+e], b = w*16+nt*8+tig*2+e

    // h-image store offsets for the 4 cells
    unsigned hoff[4];
#pragma unroll
    for (int m = 0; m < 4; ++m) {
        int b = w * 16 + (m >> 1) * 8 + tig * 2 + (m & 1);
        hoff[m] = (unsigned)kw * 16384u + (unsigned)b * 256u
                + (unsigned)(((jt & 15) ^ (b & 7)) << 4) + (unsigned)fg * 2u;
    }

    for (int t = 0; t < TT; ++t) {
        const unsigned par = (unsigned)(t & 1);

        // ---- gx prefetch (fragment order, 8 coalesced LDG.64) ----
        float2 gxv[8];
        {
            const float2* gbase = (const float2*)g_gxf + ((size_t)t * 128 + jt) * 8 * 128 + tid;
#pragma unroll
            for (int gn = 0; gn < 8; ++gn) gxv[gn] = gbase[gn * 128];
        }

        // ---- lane0 of warp w: wait + issue chunks {w, w+4} ----
        if (lane == 0) {
#pragma unroll
            for (int q = 0; q < 2; ++q) {
                int c = w + q * 4;
                if (t) { unsigned tgt = 64u * (unsigned)t;
                         while (flag_acq(&g_donec[c]) < tgt) { } }
                mbar_expect(mb[c], B_BUFSZ);
                bulk_g2s(sb + B_OFF + (unsigned)c * B_BUFSZ,
                         (const char*)&g_h16[par][0] + (size_t)c * B_BUFSZ, B_BUFSZ, mb[c]);
            }
        }

        float d[2][2][4];
#pragma unroll
        for (int mt = 0; mt < 2; ++mt)
#pragma unroll
            for (int nt2 = 0; nt2 < 2; ++nt2)
#pragma unroll
                for (int r = 0; r < 4; ++r) d[mt][nt2][r] = 0.f;

        for (int c = 0; c < 8; ++c) {
            mbar_wait(mb[c], par);
            const unsigned ahi  = aBase + (unsigned)c * 256u;
            const unsigned bbuf = sb + B_OFF + (unsigned)c * B_BUFSZ + bRowOff;
#pragma unroll
            for (int ks = 0; ks < 8; ++ks) {
                unsigned Ah0[4], Ah1[4], B[4];
                unsigned seg = ((unsigned)(ks * 2) + bHalf) ^ bMask;
                ldsm4(B,   bbuf + (seg << 4));
                ldsm4(Ah0, ahi + ks * 32u);
                ldsm4(Ah1, ahi + ks * 32u + 16u * W_STRIDE);
                mma16816(d[0][0], Ah0, B[0], B[1]);
                mma16816(d[0][1], Ah0, B[2], B[3]);
                mma16816(d[1][0], Ah1, B[0], B[1]);
                mma16816(d[1][1], Ah1, B[2], B[3]);
            }
        }

        // ---- register-resident activations (4 cells) ----
        // rows: fg->i, fg+8->f (d[0][nt][e], d[0][nt][2+e]); 16+fg->g, 24+fg->o (d[1]...)
        __half* hbase = &g_h16[(t + 1) & 1][0];
#pragma unroll
        for (int nt2 = 0; nt2 < 2; ++nt2) {
#pragma unroll
            for (int e = 0; e < 2; ++e) {
                int m = nt2 * 2 + e;
                float gi = d[0][nt2][e]     + (e ? gxv[0 + nt2].y : gxv[0 + nt2].x);
                float gf = d[0][nt2][2 + e] + (e ? gxv[2 + nt2].y : gxv[2 + nt2].x);
                float gg = d[1][nt2][e]     + (e ? gxv[4 + nt2].y : gxv[4 + nt2].x);
                float go = d[1][nt2][2 + e] + (e ? gxv[6 + nt2].y : gxv[6 + nt2].x);
                float si = sigm(gi), sf = sigm(gf), so = sigm(go);
                cc[m] = sf * cc[m] + si * tanh_fast(gg);
                float hv = so * tanh_fast(cc[m]);
                *(__half*)((char*)hbase + hoff[m]) = __float2half_rn(hv);
                if (t == TT - 1) {
                    int b = w * 16 + nt2 * 8 + tig * 2 + e;
                    g_hfin[(size_t)b * HSZ + jt * 8 + fg] = hv;
                }
            }
        }

        // ---- per-warp publish ----
        __syncwarp();
        if (lane == 0) flag_rel(&g_donec[kw]);

        // protect h buffers for next step's copy issues (all warps done reading)
        __syncthreads();
    }
}

// ---------------------------------------------------------------------------
// Classifier
// ---------------------------------------------------------------------------
__global__ __launch_bounds__(128)
void k_classifier(const float* __restrict__ Wclf,
                  const float* __restrict__ bclf,
                  float* __restrict__ out) {
    int b = blockIdx.x;
    int o = threadIdx.x;
    __shared__ float hsh[HSZ];
    for (int k = threadIdx.x; k < HSZ; k += 128) hsh[k] = g_hfin[(size_t)b * HSZ + k];
    __syncthreads();
    const float* wp = Wclf + (size_t)o * HSZ;
    float acc = 0.f;
#pragma unroll 4
    for (int k = 0; k < HSZ; k += 4) {
        float4 wv = *(const float4*)(wp + k);
        acc += wv.x * hsh[k] + wv.y * hsh[k + 1] + wv.z * hsh[k + 2] + wv.w * hsh[k + 3];
    }
    out[b * OSZ + o] = acc + bclf[o];
}

// ---------------------------------------------------------------------------
// Launch (graph-capturable: kernel launches only)
// ---------------------------------------------------------------------------
extern "C" void kernel_launch(void* const* d_in, const int* in_sizes, int n_in,
                              void* d_out, int out_size) {
    const float* x    = (const float*)d_in[0];
    const float* Wih  = (const float*)d_in[1];
    const float* Whh  = (const float*)d_in[2];
    const float* bih  = (const float*)d_in[3];
    const float* bhh  = (const float*)d_in[4];
    const float* Wclf = (const float*)d_in[5];
    const float* bclf = (const float*)d_in[6];
    float* out = (float*)d_out;

    cudaFuncSetAttribute(k_input_mma, cudaFuncAttributeMaxDynamicSharedMemorySize, IG_SMEM);
    cudaFuncSetAttribute(k_lstm,      cudaFuncAttributeMaxDynamicSharedMemorySize, SMEM_TOTAL);

    k_zero<<<256, 256>>>();
    k_prep<<<2304, 256>>>(x, Wih);
    k_input_mma<<<dim3(32, 256), 256, IG_SMEM>>>(bih, bhh);
    k_lstm<<<NCTA, NTHR, SMEM_TOTAL>>>(Whh);
    k_classifier<<<64, 128>>>(Wclf, bclf, out);
}